// round 8
// baseline (speedup 1.0000x reference)
#include <cuda_runtime.h>
#include <cstdint>
#include <cstddef>
#include <math.h>

#define H_DIM 256
#define MAXV 10000
#define LN_EPS 1e-5f

// Scratch: [node][1024] = [Uh | Vh | Ah | Bh], plus aggregation buffer.
__device__ float g_nodebuf[(size_t)MAXV * 1024];
__device__ float g_agg[(size_t)MAXV * H_DIM];
// tf32-rounded weights: [Wu | Wv | Wa | Wb | Wc], each 256x256.
__device__ float g_wtf[5 * 65536];

// No "memory" clobber — ordering via data deps; clobber kills MLP batching.
__device__ __forceinline__ void red_add_v4(float* addr, float a, float b, float c, float d) {
    asm volatile("red.global.add.v4.f32 [%0], {%1,%2,%3,%4};"
                 :: "l"(addr), "f"(a), "f"(b), "f"(c), "f"(d));
}

__device__ __forceinline__ float to_tf32(float x) {
    float y;
    asm("cvt.rna.tf32.f32 %0, %1;" : "=f"(y) : "f"(x));
    return y;
}

__device__ __forceinline__ float4 tf32_4(float4 v) {
    return make_float4(to_tf32(v.x), to_tf32(v.y), to_tf32(v.z), to_tf32(v.w));
}

__device__ __forceinline__ void mma_tf32(float& d0, float& d1, float& d2, float& d3,
                                         float a0, float a1, float a2, float a3,
                                         float b0, float b1) {
    asm volatile(
        "mma.sync.aligned.m16n8k8.row.col.f32.tf32.tf32.f32 "
        "{%0,%1,%2,%3}, {%4,%5,%6,%7}, {%8,%9}, {%0,%1,%2,%3};\n"
        : "+f"(d0), "+f"(d1), "+f"(d2), "+f"(d3)
        : "r"(__float_as_uint(a0)), "r"(__float_as_uint(a1)),
          "r"(__float_as_uint(a2)), "r"(__float_as_uint(a3)),
          "r"(__float_as_uint(b0)), "r"(__float_as_uint(b1)));
}

__device__ __forceinline__ void cpa16(uint32_t saddr, const void* g) {
    asm volatile("cp.async.cg.shared.global [%0], [%1], 16;" :: "r"(saddr), "l"(g));
}
__device__ __forceinline__ void cpa_commit() {
    asm volatile("cp.async.commit_group;");
}
template <int N>
__device__ __forceinline__ void cpa_wait() {
    asm volatile("cp.async.wait_group %0;" :: "n"(N));
}
__device__ __forceinline__ void l2_prefetch(const void* p) {
    asm volatile("prefetch.global.L2 [%0];" :: "l"(p));
}

// Stride 36: fragment load bank = (36g + t) % 32 = (4g + t) % 32, a perfect
// permutation over (g in 0..7, t in 0..3) -> conflict-free. 144B rows, 16B aligned.
#define SA_STRIDE 36
#define SB_STRIDE 36
#define SE_STRIDE 264

// smem layout (floats): A0[2304] A1[2304] B0[9216] B1[9216] = 23040 floats (92160B)
#define SA0_OFF 0
#define SA1_OFF 2304
#define SB0_OFF 4608
#define SB1_OFF 13824
#define GEMM_SMEM_BYTES 92160

// ---------------------------------------------------------------------------
// Kernel 0a: zero agg (graph-replay safe)
// ---------------------------------------------------------------------------
__global__ void zero_agg_kernel(int n4) {
    int i = blockIdx.x * blockDim.x + threadIdx.x;
    if (i < n4) reinterpret_cast<float4*>(g_agg)[i] = make_float4(0.f, 0.f, 0.f, 0.f);
}

// ---------------------------------------------------------------------------
// Kernel 0b: pre-round weights to tf32 (B operands)
// ---------------------------------------------------------------------------
__global__ void cvt_weights_kernel(
    const float* __restrict__ Wu, const float* __restrict__ Wv,
    const float* __restrict__ Wa, const float* __restrict__ Wb,
    const float* __restrict__ Wc)
{
    int i = blockIdx.x * blockDim.x + threadIdx.x;   // float4 index, 81920 total
    int m = i >> 14;                                  // 16384 float4 per matrix
    int r = i & 16383;
    const float* src = (m == 0) ? Wu : (m == 1) ? Wv : (m == 2) ? Wa : (m == 3) ? Wb : Wc;
    float4 v = __ldg(reinterpret_cast<const float4*>(src) + r);
    reinterpret_cast<float4*>(g_wtf)[i] = tf32_4(v);
}

// ---------------------------------------------------------------------------
// Kernel 1: node GEMM (tf32 mma, cp.async double-buffered)
// __launch_bounds__(256, 2): cap regs at 128 so 2 CTAs fit the 64K register file.
// ---------------------------------------------------------------------------
__global__ __launch_bounds__(256, 2) void node_gemm_tc_kernel(
    const float* __restrict__ h,
    const float* __restrict__ bu, const float* __restrict__ bv,
    const float* __restrict__ ba, const float* __restrict__ bb,
    int V)
{
    extern __shared__ float smem[];
    const uint32_t smem_u32 = (uint32_t)__cvta_generic_to_shared(smem);

    const int by = blockIdx.y;
    const float* W = g_wtf + (size_t)by * 65536;   // tf32-rounded
    const float* bias = (by == 0) ? bu : (by == 1) ? bv : (by == 2) ? ba : bb;

    const int tid  = threadIdx.x;
    const int w    = tid >> 5;
    const int lane = tid & 31;
    const int g    = lane >> 2;
    const int t    = lane & 3;
    const int row0 = blockIdx.x * 64;

    const int lr  = tid >> 2;          // 0..63
    const int lk8 = (tid & 3) * 8;     // 0,8,16,24

    int gr = row0 + lr; if (gr >= V) gr = V - 1;    // clamp (stores guarded)
    const float* arow = h + (size_t)gr * H_DIM + lk8;
    const float* brow = W + (size_t)tid * H_DIM;

    const uint32_t sa_a[2] = { smem_u32 + (SA0_OFF + lr * SA_STRIDE + lk8) * 4,
                               smem_u32 + (SA1_OFF + lr * SA_STRIDE + lk8) * 4 };
    const uint32_t sb_a[2] = { smem_u32 + (SB0_OFF + tid * SB_STRIDE) * 4,
                               smem_u32 + (SB1_OFF + tid * SB_STRIDE) * 4 };

    float acc[4][4][4];
    #pragma unroll
    for (int mt = 0; mt < 4; mt++)
        #pragma unroll
        for (int nt = 0; nt < 4; nt++)
            #pragma unroll
            for (int q = 0; q < 4; q++) acc[mt][nt][q] = 0.f;

    // prologue: stage chunk 0 into buf 0
    cpa16(sa_a[0],      arow);
    cpa16(sa_a[0] + 16, arow + 4);
    #pragma unroll
    for (int q = 0; q < 8; q++) cpa16(sb_a[0] + q * 16, brow + q * 4);
    cpa_commit();

    #pragma unroll
    for (int c = 0; c < 8; c++) {
        const int buf = c & 1;
        if (c < 7) {
            const int nbuf = buf ^ 1;
            const int kk = (c + 1) * 32;
            cpa16(sa_a[nbuf],      arow + kk);
            cpa16(sa_a[nbuf] + 16, arow + kk + 4);
            #pragma unroll
            for (int q = 0; q < 8; q++) cpa16(sb_a[nbuf] + q * 16, brow + kk + q * 4);
            cpa_commit();
            cpa_wait<1>();
        } else {
            cpa_wait<0>();
        }
        __syncthreads();

        const float* sA = smem + (buf ? SA1_OFF : SA0_OFF);
        const float* sB = smem + (buf ? SB1_OFF : SB0_OFF);
        #pragma unroll
        for (int ks = 0; ks < 4; ks++) {
            const int kb = ks * 8;
            float bf[4][2];
            #pragma unroll
            for (int nt = 0; nt < 4; nt++) {
                int n = w * 32 + nt * 8 + g;
                bf[nt][0] = sB[n * SB_STRIDE + kb + t];
                bf[nt][1] = sB[n * SB_STRIDE + kb + t + 4];
            }
            #pragma unroll
            for (int mt = 0; mt < 4; mt++) {
                int m = mt * 16;
                float a0 = sA[(m + g) * SA_STRIDE + kb + t];
                float a1 = sA[(m + g + 8) * SA_STRIDE + kb + t];
                float a2 = sA[(m + g) * SA_STRIDE + kb + t + 4];
                float a3 = sA[(m + g + 8) * SA_STRIDE + kb + t + 4];
                #pragma unroll
                for (int nt = 0; nt < 4; nt++)
                    mma_tf32(acc[mt][nt][0], acc[mt][nt][1], acc[mt][nt][2], acc[mt][nt][3],
                             a0, a1, a2, a3, bf[nt][0], bf[nt][1]);
            }
        }
        __syncthreads();
    }

    #pragma unroll
    for (int mt = 0; mt < 4; mt++) {
        #pragma unroll
        for (int nt = 0; nt < 4; nt++) {
            int cc = w * 32 + nt * 8 + 2 * t;
            int r0 = row0 + mt * 16 + g;
            int r1 = r0 + 8;
            if (r0 < V) {
                float* o = g_nodebuf + (size_t)r0 * 1024 + by * 256 + cc;
                o[0] = acc[mt][nt][0] + bias[cc];
                o[1] = acc[mt][nt][1] + bias[cc + 1];
            }
            if (r1 < V) {
                float* o = g_nodebuf + (size_t)r1 * 1024 + by * 256 + cc;
                o[0] = acc[mt][nt][2] + bias[cc];
                o[1] = acc[mt][nt][3] + bias[cc + 1];
            }
        }
    }
}

// ---------------------------------------------------------------------------
// Kernel 2: fused edge kernel (cp.async double-buffered tf32 GEMM + epilogue)
// R8: e loads use NORMAL policy (residual re-read hits L2, reuse distance =
// one block lifetime); gather footprint L2-prefetched before the mainloop.
// ---------------------------------------------------------------------------
__global__ __launch_bounds__(256, 2) void edge_fused_tc_kernel(
    const float* __restrict__ e,
    const int*   __restrict__ ei,      // [2][E]
    const float* __restrict__ bc,
    const float* __restrict__ ge, const float* __restrict__ be,
    float* __restrict__ e_out,
    int E, int V)
{
    extern __shared__ float smem[];
    const uint32_t smem_u32 = (uint32_t)__cvta_generic_to_shared(smem);
    float* sE = smem;                   // [64][264], reuses GEMM buffers post-loop

    __shared__ int   sSrc[64], sDst[64];
    __shared__ float sBc[256], sGe[256], sBe[256];

    const int tid = threadIdx.x;
    const int e0  = blockIdx.x * 64;

    if (tid < 64) {
        sSrc[tid] = ei[e0 + tid];
        sDst[tid] = ei[E + e0 + tid];
    }
    sBc[tid] = bc[tid]; sGe[tid] = ge[tid]; sBe[tid] = be[tid];

    const int w    = tid >> 5;
    const int lane = tid & 31;
    const int g    = lane >> 2;
    const int t    = lane & 3;
    const int col0 = lane * 8;

    const int lr  = tid >> 2;
    const int lk8 = (tid & 3) * 8;

    const float* Wcv = g_wtf + 4 * 65536;           // tf32-rounded Wc
    const float* arow = e + (size_t)(e0 + lr) * H_DIM + lk8;   // E % 64 == 0
    const float* brow = Wcv + (size_t)tid * H_DIM;

    const uint32_t sa_a[2] = { smem_u32 + (SA0_OFF + lr * SA_STRIDE + lk8) * 4,
                               smem_u32 + (SA1_OFF + lr * SA_STRIDE + lk8) * 4 };
    const uint32_t sb_a[2] = { smem_u32 + (SB0_OFF + tid * SB_STRIDE) * 4,
                               smem_u32 + (SB1_OFF + tid * SB_STRIDE) * 4 };

    float acc[4][4][4];
    #pragma unroll
    for (int mt = 0; mt < 4; mt++)
        #pragma unroll
        for (int nt = 0; nt < 4; nt++)
            #pragma unroll
            for (int q = 0; q < 4; q++) acc[mt][nt][q] = 0.f;

    // prologue (normal L2 policy; e rows stay resident for the residual read)
    cpa16(sa_a[0],      arow);
    cpa16(sa_a[0] + 16, arow + 4);
    #pragma unroll
    for (int q = 0; q < 8; q++) cpa16(sb_a[0] + q * 16, brow + q * 4);
    cpa_commit();

    // Make sSrc/sDst visible, then prewarm the epilogue gather footprint in L2
    // while the GEMM mainloop runs. Zero register cost, fire-and-forget.
    __syncthreads();
    #pragma unroll
    for (int i = 0; i < 8; i++) {
        const int r = w * 8 + i;
        const int s = sSrc[r];
        const int d = sDst[r];
        l2_prefetch(g_nodebuf + (size_t)d * 1024 + 512 + col0);  // Ah[dst]
        l2_prefetch(g_nodebuf + (size_t)s * 1024 + 768 + col0);  // Bh[src]
        l2_prefetch(g_nodebuf + (size_t)d * 1024 + 256 + col0);  // Vh[dst]
    }

    #pragma unroll
    for (int c = 0; c < 8; c++) {
        const int buf = c & 1;
        if (c < 7) {
            const int nbuf = buf ^ 1;
            const int kk = (c + 1) * 32;
            cpa16(sa_a[nbuf],      arow + kk);
            cpa16(sa_a[nbuf] + 16, arow + kk + 4);
            #pragma unroll
            for (int q = 0; q < 8; q++) cpa16(sb_a[nbuf] + q * 16, brow + kk + q * 4);
            cpa_commit();
            cpa_wait<1>();
        } else {
            cpa_wait<0>();
        }
        __syncthreads();

        const float* sA = smem + (buf ? SA1_OFF : SA0_OFF);
        const float* sB = smem + (buf ? SB1_OFF : SB0_OFF);
        #pragma unroll
        for (int ks = 0; ks < 4; ks++) {
            const int kb = ks * 8;
            float bf[4][2];
            #pragma unroll
            for (int nt = 0; nt < 4; nt++) {
                int n = w * 32 + nt * 8 + g;
                bf[nt][0] = sB[n * SB_STRIDE + kb + t];
                bf[nt][1] = sB[n * SB_STRIDE + kb + t + 4];
            }
            #pragma unroll
            for (int mt = 0; mt < 4; mt++) {
                int m = mt * 16;
                float a0 = sA[(m + g) * SA_STRIDE + kb + t];
                float a1 = sA[(m + g + 8) * SA_STRIDE + kb + t];
                float a2 = sA[(m + g) * SA_STRIDE + kb + t + 4];
                float a3 = sA[(m + g + 8) * SA_STRIDE + kb + t + 4];
                #pragma unroll
                for (int nt = 0; nt < 4; nt++)
                    mma_tf32(acc[mt][nt][0], acc[mt][nt][1], acc[mt][nt][2], acc[mt][nt][3],
                             a0, a1, a2, a3, bf[nt][0], bf[nt][1]);
            }
        }
        __syncthreads();
    }

    // Stage Ce fragments into sE (reuses GEMM buffers; all smem reads done)
    #pragma unroll
    for (int mt = 0; mt < 4; mt++) {
        #pragma unroll
        for (int nt = 0; nt < 4; nt++) {
            int r = mt * 16 + g;
            int cc = w * 32 + nt * 8 + 2 * t;
            sE[r * SE_STRIDE + cc]       = acc[mt][nt][0];
            sE[r * SE_STRIDE + cc + 1]   = acc[mt][nt][1];
            sE[(r + 8) * SE_STRIDE + cc]     = acc[mt][nt][2];
            sE[(r + 8) * SE_STRIDE + cc + 1] = acc[mt][nt][3];
        }
    }
    __syncthreads();

    // ---- fused epilogue: warp w owns rows w*8..w*8+7 fully ----
    #pragma unroll
    for (int i = 0; i < 8; i++) {
        const int r = w * 8 + i;
        const int er = e0 + r;
        const int s = sSrc[r];
        const int d = sDst[r];
        const float4* ah = reinterpret_cast<const float4*>(g_nodebuf + (size_t)d * 1024 + 512 + col0);
        const float4* bh = reinterpret_cast<const float4*>(g_nodebuf + (size_t)s * 1024 + 768 + col0);
        const float4* vh = reinterpret_cast<const float4*>(g_nodebuf + (size_t)d * 1024 + 256 + col0);

        float4 a0 = __ldg(ah), a1 = __ldg(ah + 1);
        float4 b0 = __ldg(bh), b1 = __ldg(bh + 1);
        float4 v0 = __ldg(vh), v1 = __ldg(vh + 1);
        float4 er0 = __ldg(reinterpret_cast<const float4*>(e + (size_t)er * H_DIM + col0));
        float4 er1 = __ldg(reinterpret_cast<const float4*>(e + (size_t)er * H_DIM + col0 + 4));

        float x[8], vhv[8], erv[8];
        {
            const float* se = sE + r * SE_STRIDE + col0;
            float4 u0 = *reinterpret_cast<const float4*>(se);
            float4 u1 = *reinterpret_cast<const float4*>(se + 4);
            x[0] = u0.x + a0.x + b0.x; x[1] = u0.y + a0.y + b0.y;
            x[2] = u0.z + a0.z + b0.z; x[3] = u0.w + a0.w + b0.w;
            x[4] = u1.x + a1.x + b1.x; x[5] = u1.y + a1.y + b1.y;
            x[6] = u1.z + a1.z + b1.z; x[7] = u1.w + a1.w + b1.w;
        }
        vhv[0] = v0.x; vhv[1] = v0.y; vhv[2] = v0.z; vhv[3] = v0.w;
        vhv[4] = v1.x; vhv[5] = v1.y; vhv[6] = v1.z; vhv[7] = v1.w;
        erv[0] = er0.x; erv[1] = er0.y; erv[2] = er0.z; erv[3] = er0.w;
        erv[4] = er1.x; erv[5] = er1.y; erv[6] = er1.z; erv[7] = er1.w;

        float sum = 0.f, sq = 0.f;
        #pragma unroll
        for (int cc = 0; cc < 8; cc++) {
            float xv = x[cc] + sBc[col0 + cc];
            x[cc] = xv;
            sum += xv;
            sq  += xv * xv;
        }

        float gv[8];
        #pragma unroll
        for (int cc = 0; cc < 8; cc++) {
            float gt = 1.f / (1.f + __expf(-x[cc]));
            gv[cc] = gt * vhv[cc];
        }
        float* ag = g_agg + (size_t)s * H_DIM + col0;
        red_add_v4(ag,     gv[0], gv[1], gv[2], gv[3]);
        red_add_v4(ag + 4, gv[4], gv[5], gv[6], gv[7]);

        #pragma unroll
        for (int off = 16; off > 0; off >>= 1) {
            sum += __shfl_xor_sync(0xFFFFFFFFu, sum, off);
            sq  += __shfl_xor_sync(0xFFFFFFFFu, sq,  off);
        }
        const float mu  = sum * (1.f / 256.f);
        const float var = sq * (1.f / 256.f) - mu * mu;
        const float rs  = rsqrtf(var + LN_EPS);

        float4 o0, o1;
        float* ov0 = &o0.x; float* ov1 = &o1.x;
        #pragma unroll
        for (int cc = 0; cc < 4; cc++) {
            float y = (x[cc] - mu) * rs * sGe[col0 + cc] + sBe[col0 + cc];
            y = y > 0.f ? y : 0.f;
            ov0[cc] = erv[cc] + y;
        }
        #pragma unroll
        for (int cc = 0; cc < 4; cc++) {
            float y = (x[cc + 4] - mu) * rs * sGe[col0 + cc + 4] + sBe[col0 + cc + 4];
            y = y > 0.f ? y : 0.f;
            ov1[cc] = erv[cc + 4] + y;
        }
        float4* orow = reinterpret_cast<float4*>(e_out + (size_t)er * H_DIM + col0);
        __stcs(orow, o0);
        __stcs(orow + 1, o1);
    }
}

// ---------------------------------------------------------------------------
// Kernel 3: node epilogue  h_out = h + relu(LN(Uh + agg))
// ---------------------------------------------------------------------------
__global__ __launch_bounds__(256) void node_epilogue_kernel(
    const float* __restrict__ h,
    const float* __restrict__ gh, const float* __restrict__ bhv,
    float* __restrict__ h_out, int V)
{
    const int warp = threadIdx.x >> 5;
    const int lane = threadIdx.x & 31;
    const int n = blockIdx.x * 8 + warp;
    if (n >= V) return;
    const int col0 = lane * 8;

    const float4* u  = reinterpret_cast<const float4*>(g_nodebuf + (size_t)n * 1024 + col0);
    const float4* ag = reinterpret_cast<const float4*>(g_agg     + (size_t)n * H_DIM + col0);
    const float4* hr = reinterpret_cast<const float4*>(h         + (size_t)n * H_DIM + col0);

    float4 u0 = __ldcs(u),  u1 = __ldcs(u + 1);
    float4 g0 = __ldcs(ag), g1 = __ldcs(ag + 1);
    float4 h0 = __ldcs(hr), h1 = __ldcs(hr + 1);

    float x[8], hv[8];
    x[0] = u0.x + g0.x; x[1] = u0.y + g0.y; x[2] = u0.z + g0.z; x[3] = u0.w + g0.w;
    x[4] = u1.x + g1.x; x[5] = u1.y + g1.y; x[6] = u1.z + g1.z; x[7] = u1.w + g1.w;
    hv[0] = h0.x; hv[1] = h0.y; hv[2] = h0.z; hv[3] = h0.w;
    hv[4] = h1.x; hv[5] = h1.y; hv[6] = h1.z; hv[7] = h1.w;

    float sum = 0.f, sq = 0.f;
    #pragma unroll
    for (int c = 0; c < 8; c++) { sum += x[c]; sq += x[c] * x[c]; }
    #pragma unroll
    for (int off = 16; off > 0; off >>= 1) {
        sum += __shfl_xor_sync(0xFFFFFFFFu, sum, off);
        sq  += __shfl_xor_sync(0xFFFFFFFFu, sq,  off);
    }
    const float mu  = sum * (1.f / 256.f);
    const float var = sq * (1.f / 256.f) - mu * mu;
    const float rs  = rsqrtf(var + LN_EPS);

    float4 o0, o1;
    float* ov0 = &o0.x; float* ov1 = &o1.x;
    #pragma unroll
    for (int c = 0; c < 4; c++) {
        float y = (x[c] - mu) * rs * gh[col0 + c] + bhv[col0 + c];
        y = y > 0.f ? y : 0.f;
        ov0[c] = hv[c] + y;
    }
    #pragma unroll
    for (int c = 0; c < 4; c++) {
        float y = (x[c + 4] - mu) * rs * gh[col0 + c + 4] + bhv[col0 + c + 4];
        y = y > 0.f ? y : 0.f;
        ov1[c] = hv[c + 4] + y;
    }
    float4* o = reinterpret_cast<float4*>(h_out + (size_t)n * H_DIM + col0);
    __stcs(o, o0);
    __stcs(o + 1, o1);
}

// ---------------------------------------------------------------------------
extern "C" void kernel_launch(void* const* d_in, const int* in_sizes, int n_in,
                              void* d_out, int out_size)
{
    const float* h  = (const float*)d_in[0];
    const float* e  = (const float*)d_in[1];
    const int*   ei = (const int*)  d_in[2];
    const float* Wu = (const float*)d_in[3];
    const float* bu = (const float*)d_in[4];
    const float* Wv = (const float*)d_in[5];
    const float* bv = (const float*)d_in[6];
    const float* Wa = (const float*)d_in[7];
    const float* ba = (const float*)d_in[8];
    const float* Wb = (const float*)d_in[9];
    const float* bb = (const float*)d_in[10];
    const float* Wc = (const float*)d_in[11];
    const float* bc = (const float*)d_in[12];
    const float* gh = (const float*)d_in[13];
    const float* bh = (const float*)d_in[14];
    const float* ge = (const float*)d_in[15];
    const float* be = (const float*)d_in[16];

    const int V = in_sizes[0] / H_DIM;
    const int E = in_sizes[1] / H_DIM;

    float* h_out = (float*)d_out;
    float* e_out = (float*)d_out + (size_t)V * H_DIM;

    static int attr_set = 0;
    if (!attr_set) {
        cudaFuncSetAttribute(node_gemm_tc_kernel,
                             cudaFuncAttributeMaxDynamicSharedMemorySize, GEMM_SMEM_BYTES);
        cudaFuncSetAttribute(edge_fused_tc_kernel,
                             cudaFuncAttributeMaxDynamicSharedMemorySize, GEMM_SMEM_BYTES);
        attr_set = 1;
    }

    const int n4 = V * (H_DIM / 4);
    zero_agg_kernel<<<(n4 + 255) / 256, 256>>>(n4);
    cvt_weights_kernel<<<320, 256>>>(Wu, Wv, Wa, Wb, Wc);

    dim3 g1((V + 63) / 64, 4);
    node_gemm_tc_kernel<<<g1, 256, GEMM_SMEM_BYTES>>>(h, bu, bv, ba, bb, V);

    edge_fused_tc_kernel<<<E / 64, 256, GEMM_SMEM_BYTES>>>(e, ei, bc, ge, be, e_out, E, V);

    node_epilogue_kernel<<<(V + 7) / 8, 256>>>(h, gh, bh, h_out, V);
}

// round 9
// speedup vs baseline: 1.0622x; 1.0622x over previous
#include <cuda_runtime.h>
#include <cstdint>
#include <cstddef>
#include <math.h>

#define H_DIM 256
#define MAXV 10000
#define MAXE 160000
#define LN_EPS 1e-5f

// Scratch: [node][1024] = [Uh | Vh | Ah | Bh], aggregation buffer, Ce buffer.
__device__ float g_nodebuf[(size_t)MAXV * 1024];
__device__ float g_agg[(size_t)MAXV * H_DIM];
__device__ float g_ce[(size_t)MAXE * H_DIM];
// tf32-rounded weights: [Wu | Wv | Wa | Wb | Wc], each 256x256.
__device__ float g_wtf[5 * 65536];

// No "memory" clobber — ordering via data deps; clobber kills MLP batching.
__device__ __forceinline__ void red_add_v4(float* addr, float a, float b, float c, float d) {
    asm volatile("red.global.add.v4.f32 [%0], {%1,%2,%3,%4};"
                 :: "l"(addr), "f"(a), "f"(b), "f"(c), "f"(d));
}

__device__ __forceinline__ float to_tf32(float x) {
    float y;
    asm("cvt.rna.tf32.f32 %0, %1;" : "=f"(y) : "f"(x));
    return y;
}

__device__ __forceinline__ float4 tf32_4(float4 v) {
    return make_float4(to_tf32(v.x), to_tf32(v.y), to_tf32(v.z), to_tf32(v.w));
}

__device__ __forceinline__ void mma_tf32(float& d0, float& d1, float& d2, float& d3,
                                         float a0, float a1, float a2, float a3,
                                         float b0, float b1) {
    asm volatile(
        "mma.sync.aligned.m16n8k8.row.col.f32.tf32.tf32.f32 "
        "{%0,%1,%2,%3}, {%4,%5,%6,%7}, {%8,%9}, {%0,%1,%2,%3};\n"
        : "+f"(d0), "+f"(d1), "+f"(d2), "+f"(d3)
        : "r"(__float_as_uint(a0)), "r"(__float_as_uint(a1)),
          "r"(__float_as_uint(a2)), "r"(__float_as_uint(a3)),
          "r"(__float_as_uint(b0)), "r"(__float_as_uint(b1)));
}

__device__ __forceinline__ void cpa16(uint32_t saddr, const void* g) {
    asm volatile("cp.async.cg.shared.global [%0], [%1], 16;" :: "r"(saddr), "l"(g));
}
__device__ __forceinline__ void cpa_commit() {
    asm volatile("cp.async.commit_group;");
}
template <int N>
__device__ __forceinline__ void cpa_wait() {
    asm volatile("cp.async.wait_group %0;" :: "n"(N));
}

// Stride 36: fragment bank = (4g + t) % 32, perfect permutation -> conflict-free.
#define SA_STRIDE 36
#define SB_STRIDE 36

// ---------------------------------------------------------------------------
// Kernel 0a: zero agg (graph-replay safe)
// ---------------------------------------------------------------------------
__global__ void zero_agg_kernel(int n4) {
    int i = blockIdx.x * blockDim.x + threadIdx.x;
    if (i < n4) reinterpret_cast<float4*>(g_agg)[i] = make_float4(0.f, 0.f, 0.f, 0.f);
}

// ---------------------------------------------------------------------------
// Kernel 0b: pre-round weights to tf32 (B operands)
// ---------------------------------------------------------------------------
__global__ void cvt_weights_kernel(
    const float* __restrict__ Wu, const float* __restrict__ Wv,
    const float* __restrict__ Wa, const float* __restrict__ Wb,
    const float* __restrict__ Wc)
{
    int i = blockIdx.x * blockDim.x + threadIdx.x;   // float4 index, 81920 total
    int m = i >> 14;
    int r = i & 16383;
    const float* src = (m == 0) ? Wu : (m == 1) ? Wv : (m == 2) ? Wa : (m == 3) ? Wb : Wc;
    float4 v = __ldg(reinterpret_cast<const float4*>(src) + r);
    reinterpret_cast<float4*>(g_wtf)[i] = tf32_4(v);
}

// ---------------------------------------------------------------------------
// Kernel 1: node GEMM (tf32 mma, cp.async double-buffered, 64x256 tile)
// (unchanged R7 structure: 2 CTAs/SM)
// smem floats: A0[2304] A1[2304] B0[9216] B1[9216] = 92160B
// ---------------------------------------------------------------------------
#define NG_SA0 0
#define NG_SA1 2304
#define NG_SB0 4608
#define NG_SB1 13824
#define NG_SMEM_BYTES 92160

__global__ __launch_bounds__(256, 2) void node_gemm_tc_kernel(
    const float* __restrict__ h,
    const float* __restrict__ bu, const float* __restrict__ bv,
    const float* __restrict__ ba, const float* __restrict__ bb,
    int V)
{
    extern __shared__ float smem[];
    const uint32_t smem_u32 = (uint32_t)__cvta_generic_to_shared(smem);

    const int by = blockIdx.y;
    const float* W = g_wtf + (size_t)by * 65536;
    const float* bias = (by == 0) ? bu : (by == 1) ? bv : (by == 2) ? ba : bb;

    const int tid  = threadIdx.x;
    const int w    = tid >> 5;
    const int lane = tid & 31;
    const int g    = lane >> 2;
    const int t    = lane & 3;
    const int row0 = blockIdx.x * 64;

    const int lr  = tid >> 2;
    const int lk8 = (tid & 3) * 8;

    int gr = row0 + lr; if (gr >= V) gr = V - 1;
    const float* arow = h + (size_t)gr * H_DIM + lk8;
    const float* brow = W + (size_t)tid * H_DIM;

    const uint32_t sa_a[2] = { smem_u32 + (NG_SA0 + lr * SA_STRIDE + lk8) * 4,
                               smem_u32 + (NG_SA1 + lr * SA_STRIDE + lk8) * 4 };
    const uint32_t sb_a[2] = { smem_u32 + (NG_SB0 + tid * SB_STRIDE) * 4,
                               smem_u32 + (NG_SB1 + tid * SB_STRIDE) * 4 };

    float acc[4][4][4];
    #pragma unroll
    for (int mt = 0; mt < 4; mt++)
        #pragma unroll
        for (int nt = 0; nt < 4; nt++)
            #pragma unroll
            for (int q = 0; q < 4; q++) acc[mt][nt][q] = 0.f;

    cpa16(sa_a[0],      arow);
    cpa16(sa_a[0] + 16, arow + 4);
    #pragma unroll
    for (int q = 0; q < 8; q++) cpa16(sb_a[0] + q * 16, brow + q * 4);
    cpa_commit();

    #pragma unroll
    for (int c = 0; c < 8; c++) {
        const int buf = c & 1;
        if (c < 7) {
            const int nbuf = buf ^ 1;
            const int kk = (c + 1) * 32;
            cpa16(sa_a[nbuf],      arow + kk);
            cpa16(sa_a[nbuf] + 16, arow + kk + 4);
            #pragma unroll
            for (int q = 0; q < 8; q++) cpa16(sb_a[nbuf] + q * 16, brow + kk + q * 4);
            cpa_commit();
            cpa_wait<1>();
        } else {
            cpa_wait<0>();
        }
        __syncthreads();

        const float* sA = smem + (buf ? NG_SA1 : NG_SA0);
        const float* sB = smem + (buf ? NG_SB1 : NG_SB0);
        #pragma unroll
        for (int ks = 0; ks < 4; ks++) {
            const int kb = ks * 8;
            float bf[4][2];
            #pragma unroll
            for (int nt = 0; nt < 4; nt++) {
                int n = w * 32 + nt * 8 + g;
                bf[nt][0] = sB[n * SB_STRIDE + kb + t];
                bf[nt][1] = sB[n * SB_STRIDE + kb + t + 4];
            }
            #pragma unroll
            for (int mt = 0; mt < 4; mt++) {
                int m = mt * 16;
                float a0 = sA[(m + g) * SA_STRIDE + kb + t];
                float a1 = sA[(m + g + 8) * SA_STRIDE + kb + t];
                float a2 = sA[(m + g) * SA_STRIDE + kb + t + 4];
                float a3 = sA[(m + g + 8) * SA_STRIDE + kb + t + 4];
                #pragma unroll
                for (int nt = 0; nt < 4; nt++)
                    mma_tf32(acc[mt][nt][0], acc[mt][nt][1], acc[mt][nt][2], acc[mt][nt][3],
                             a0, a1, a2, a3, bf[nt][0], bf[nt][1]);
            }
        }
        __syncthreads();
    }

    #pragma unroll
    for (int mt = 0; mt < 4; mt++) {
        #pragma unroll
        for (int nt = 0; nt < 4; nt++) {
            int cc = w * 32 + nt * 8 + 2 * t;
            int r0 = row0 + mt * 16 + g;
            int r1 = r0 + 8;
            if (r0 < V) {
                float* o = g_nodebuf + (size_t)r0 * 1024 + by * 256 + cc;
                o[0] = acc[mt][nt][0] + bias[cc];
                o[1] = acc[mt][nt][1] + bias[cc + 1];
            }
            if (r1 < V) {
                float* o = g_nodebuf + (size_t)r1 * 1024 + by * 256 + cc;
                o[0] = acc[mt][nt][2] + bias[cc];
                o[1] = acc[mt][nt][3] + bias[cc + 1];
            }
        }
    }
}

// ---------------------------------------------------------------------------
// Kernel 2a: edge GEMM -> g_ce.  Tile 64 edges x 128 cols, 32 accs/thread,
// 3 CTAs/SM (24 warps). grid = (2, E/64): n-half fastest so sibling blocks
// reuse the same A rows in L2.
// smem floats: A0[2304] A1[2304] B0[4608] B1[9216..] = 13824 floats (55296B)
// ---------------------------------------------------------------------------
#define EG_SA0 0
#define EG_SA1 2304
#define EG_SB0 4608
#define EG_SB1 9216
#define EG_SMEM_BYTES 55296

__global__ __launch_bounds__(256, 3) void edge_gemm_kernel(
    const float* __restrict__ e, int E)
{
    extern __shared__ float smem[];
    const uint32_t smem_u32 = (uint32_t)__cvta_generic_to_shared(smem);

    const int nb = blockIdx.x;           // n-half: 0 or 1
    const int e0 = blockIdx.y * 64;

    const int tid  = threadIdx.x;
    const int w    = tid >> 5;
    const int lane = tid & 31;
    const int g    = lane >> 2;
    const int t    = lane & 3;
    const int wm   = w >> 2;             // 0..1: warp m-group (32 rows)
    const int wn   = w & 3;              // 0..3: warp n-group (32 cols)

    const int lr  = tid >> 2;            // A staging: row 0..63
    const int lk8 = (tid & 3) * 8;
    const int br  = tid >> 1;            // B staging: row 0..127
    const int bh8 = (tid & 1) * 16;      // k-offset 0 or 16

    const float* Wcv = g_wtf + 4 * 65536 + (size_t)(nb * 128) * H_DIM;
    const float* arow = e + (size_t)(e0 + lr) * H_DIM + lk8;   // E % 64 == 0
    const float* brow = Wcv + (size_t)br * H_DIM + bh8;

    const uint32_t sa_a[2] = { smem_u32 + (EG_SA0 + lr * SA_STRIDE + lk8) * 4,
                               smem_u32 + (EG_SA1 + lr * SA_STRIDE + lk8) * 4 };
    const uint32_t sb_a[2] = { smem_u32 + (EG_SB0 + br * SB_STRIDE + bh8) * 4,
                               smem_u32 + (EG_SB1 + br * SB_STRIDE + bh8) * 4 };

    float acc[2][4][4];
    #pragma unroll
    for (int mt = 0; mt < 2; mt++)
        #pragma unroll
        for (int nt = 0; nt < 4; nt++)
            #pragma unroll
            for (int q = 0; q < 4; q++) acc[mt][nt][q] = 0.f;

    // prologue: chunk 0 -> buf 0
    cpa16(sa_a[0],      arow);
    cpa16(sa_a[0] + 16, arow + 4);
    #pragma unroll
    for (int q = 0; q < 4; q++) cpa16(sb_a[0] + q * 16, brow + q * 4);
    cpa_commit();

    #pragma unroll
    for (int c = 0; c < 8; c++) {
        const int buf = c & 1;
        if (c < 7) {
            const int nbuf = buf ^ 1;
            const int kk = (c + 1) * 32;
            cpa16(sa_a[nbuf],      arow + kk);
            cpa16(sa_a[nbuf] + 16, arow + kk + 4);
            #pragma unroll
            for (int q = 0; q < 4; q++) cpa16(sb_a[nbuf] + q * 16, brow + kk + q * 4);
            cpa_commit();
            cpa_wait<1>();
        } else {
            cpa_wait<0>();
        }
        __syncthreads();

        const float* sA = smem + (buf ? EG_SA1 : EG_SA0);
        const float* sB = smem + (buf ? EG_SB1 : EG_SB0);
        #pragma unroll
        for (int ks = 0; ks < 4; ks++) {
            const int kb = ks * 8;
            float bf[4][2];
            #pragma unroll
            for (int nt = 0; nt < 4; nt++) {
                int n = wn * 32 + nt * 8 + g;
                bf[nt][0] = sB[n * SB_STRIDE + kb + t];
                bf[nt][1] = sB[n * SB_STRIDE + kb + t + 4];
            }
            #pragma unroll
            for (int mt = 0; mt < 2; mt++) {
                int m = wm * 32 + mt * 16;
                float a0 = sA[(m + g) * SA_STRIDE + kb + t];
                float a1 = sA[(m + g + 8) * SA_STRIDE + kb + t];
                float a2 = sA[(m + g) * SA_STRIDE + kb + t + 4];
                float a3 = sA[(m + g + 8) * SA_STRIDE + kb + t + 4];
                #pragma unroll
                for (int nt = 0; nt < 4; nt++)
                    mma_tf32(acc[mt][nt][0], acc[mt][nt][1], acc[mt][nt][2], acc[mt][nt][3],
                             a0, a1, a2, a3, bf[nt][0], bf[nt][1]);
            }
        }
        __syncthreads();
    }

    // store Ce (streaming; consumed once by the epilogue kernel)
    #pragma unroll
    for (int mt = 0; mt < 2; mt++) {
        #pragma unroll
        for (int nt = 0; nt < 4; nt++) {
            int col = nb * 128 + wn * 32 + nt * 8 + 2 * t;
            int r0 = wm * 32 + mt * 16 + g;
            float* o0 = g_ce + (size_t)(e0 + r0) * H_DIM + col;
            float* o1 = g_ce + (size_t)(e0 + r0 + 8) * H_DIM + col;
            float2 v0 = make_float2(acc[mt][nt][0], acc[mt][nt][1]);
            float2 v1 = make_float2(acc[mt][nt][2], acc[mt][nt][3]);
            __stcs(reinterpret_cast<float2*>(o0), v0);
            __stcs(reinterpret_cast<float2*>(o1), v1);
        }
    }
}

// ---------------------------------------------------------------------------
// Kernel 2b: edge epilogue. One warp per edge row; high occupancy (~5 CTAs/SM)
// hides gather/atomic latency.
// ---------------------------------------------------------------------------
__global__ __launch_bounds__(256) void edge_epilogue_kernel(
    const float* __restrict__ e,
    const int*   __restrict__ ei,
    const float* __restrict__ bc,
    const float* __restrict__ ge, const float* __restrict__ be,
    float* __restrict__ e_out,
    int E)
{
    __shared__ float sBc[256], sGe[256], sBe[256];
    const int tid = threadIdx.x;
    sBc[tid] = bc[tid]; sGe[tid] = ge[tid]; sBe[tid] = be[tid];
    __syncthreads();

    const int warp = tid >> 5;
    const int lane = tid & 31;
    const int col0 = lane * 8;
    const int er = blockIdx.x * 8 + warp;   // E % 8 == 0

    const int s = __ldg(ei + er);
    const int d = __ldg(ei + E + er);

    const float4* cep = reinterpret_cast<const float4*>(g_ce + (size_t)er * H_DIM + col0);
    const float4* ah = reinterpret_cast<const float4*>(g_nodebuf + (size_t)d * 1024 + 512 + col0);
    const float4* bh = reinterpret_cast<const float4*>(g_nodebuf + (size_t)s * 1024 + 768 + col0);
    const float4* vh = reinterpret_cast<const float4*>(g_nodebuf + (size_t)d * 1024 + 256 + col0);
    const float4* erp = reinterpret_cast<const float4*>(e + (size_t)er * H_DIM + col0);

    float4 c0 = __ldcs(cep), c1 = __ldcs(cep + 1);
    float4 a0 = __ldg(ah),   a1 = __ldg(ah + 1);
    float4 b0 = __ldg(bh),   b1 = __ldg(bh + 1);
    float4 v0 = __ldg(vh),   v1 = __ldg(vh + 1);
    float4 r0 = __ldcs(erp), r1 = __ldcs(erp + 1);

    float x[8], vhv[8], erv[8];
    x[0] = c0.x + a0.x + b0.x; x[1] = c0.y + a0.y + b0.y;
    x[2] = c0.z + a0.z + b0.z; x[3] = c0.w + a0.w + b0.w;
    x[4] = c1.x + a1.x + b1.x; x[5] = c1.y + a1.y + b1.y;
    x[6] = c1.z + a1.z + b1.z; x[7] = c1.w + a1.w + b1.w;
    vhv[0] = v0.x; vhv[1] = v0.y; vhv[2] = v0.z; vhv[3] = v0.w;
    vhv[4] = v1.x; vhv[5] = v1.y; vhv[6] = v1.z; vhv[7] = v1.w;
    erv[0] = r0.x; erv[1] = r0.y; erv[2] = r0.z; erv[3] = r0.w;
    erv[4] = r1.x; erv[5] = r1.y; erv[6] = r1.z; erv[7] = r1.w;

    float sum = 0.f, sq = 0.f;
    #pragma unroll
    for (int c = 0; c < 8; c++) {
        float xv = x[c] + sBc[col0 + c];
        x[c] = xv;
        sum += xv;
        sq  += xv * xv;
    }

    float gv[8];
    #pragma unroll
    for (int c = 0; c < 8; c++) {
        float gt = 1.f / (1.f + __expf(-x[c]));
        gv[c] = gt * vhv[c];
    }
    float* ag = g_agg + (size_t)s * H_DIM + col0;
    red_add_v4(ag,     gv[0], gv[1], gv[2], gv[3]);
    red_add_v4(ag + 4, gv[4], gv[5], gv[6], gv[7]);

    #pragma unroll
    for (int off = 16; off > 0; off >>= 1) {
        sum += __shfl_xor_sync(0xFFFFFFFFu, sum, off);
        sq  += __shfl_xor_sync(0xFFFFFFFFu, sq,  off);
    }
    const float mu  = sum * (1.f / 256.f);
    const float var = sq * (1.f / 256.f) - mu * mu;
    const float rs  = rsqrtf(var + LN_EPS);

    float4 o0, o1;
    float* ov0 = &o0.x; float* ov1 = &o1.x;
    #pragma unroll
    for (int c = 0; c < 4; c++) {
        float y = (x[c] - mu) * rs * sGe[col0 + c] + sBe[col0 + c];
        y = y > 0.f ? y : 0.f;
        ov0[c] = erv[c] + y;
    }
    #pragma unroll
    for (int c = 0; c < 4; c++) {
        float y = (x[c + 4] - mu) * rs * sGe[col0 + c + 4] + sBe[col0 + c + 4];
        y = y > 0.f ? y : 0.f;
        ov1[c] = erv[c + 4] + y;
    }
    float4* orow = reinterpret_cast<float4*>(e_out + (size_t)er * H_DIM + col0);
    __stcs(orow, o0);
    __stcs(orow + 1, o1);
}

// ---------------------------------------------------------------------------
// Kernel 3: node epilogue  h_out = h + relu(LN(Uh + agg))
// ---------------------------------------------------------------------------
__global__ __launch_bounds__(256) void node_epilogue_kernel(
    const float* __restrict__ h,
    const float* __restrict__ gh, const float* __restrict__ bhv,
    float* __restrict__ h_out, int V)
{
    const int warp = threadIdx.x >> 5;
    const int lane = threadIdx.x & 31;
    const int n = blockIdx.x * 8 + warp;
    if (n >= V) return;
    const int col0 = lane * 8;

    const float4* u  = reinterpret_cast<const float4*>(g_nodebuf + (size_t)n * 1024 + col0);
    const float4* ag = reinterpret_cast<const float4*>(g_agg     + (size_t)n * H_DIM + col0);
    const float4* hr = reinterpret_cast<const float4*>(h         + (size_t)n * H_DIM + col0);

    float4 u0 = __ldcs(u),  u1 = __ldcs(u + 1);
    float4 g0 = __ldcs(ag), g1 = __ldcs(ag + 1);
    float4 h0 = __ldcs(hr), h1 = __ldcs(hr + 1);

    float x[8], hv[8];
    x[0] = u0.x + g0.x; x[1] = u0.y + g0.y; x[2] = u0.z + g0.z; x[3] = u0.w + g0.w;
    x[4] = u1.x + g1.x; x[5] = u1.y + g1.y; x[6] = u1.z + g1.z; x[7] = u1.w + g1.w;
    hv[0] = h0.x; hv[1] = h0.y; hv[2] = h0.z; hv[3] = h0.w;
    hv[4] = h1.x; hv[5] = h1.y; hv[6] = h1.z; hv[7] = h1.w;

    float sum = 0.f, sq = 0.f;
    #pragma unroll
    for (int c = 0; c < 8; c++) { sum += x[c]; sq += x[c] * x[c]; }
    #pragma unroll
    for (int off = 16; off > 0; off >>= 1) {
        sum += __shfl_xor_sync(0xFFFFFFFFu, sum, off);
        sq  += __shfl_xor_sync(0xFFFFFFFFu, sq,  off);
    }
    const float mu  = sum * (1.f / 256.f);
    const float var = sq * (1.f / 256.f) - mu * mu;
    const float rs  = rsqrtf(var + LN_EPS);

    float4 o0, o1;
    float* ov0 = &o0.x; float* ov1 = &o1.x;
    #pragma unroll
    for (int c = 0; c < 4; c++) {
        float y = (x[c] - mu) * rs * gh[col0 + c] + bhv[col0 + c];
        y = y > 0.f ? y : 0.f;
        ov0[c] = hv[c] + y;
    }
    #pragma unroll
    for (int c = 0; c < 4; c++) {
        float y = (x[c + 4] - mu) * rs * gh[col0 + c + 4] + bhv[col0 + c + 4];
        y = y > 0.f ? y : 0.f;
        ov1[c] = hv[c + 4] + y;
    }
    float4* o = reinterpret_cast<float4*>(h_out + (size_t)n * H_DIM + col0);
    __stcs(o, o0);
    __stcs(o + 1, o1);
}

// ---------------------------------------------------------------------------
extern "C" void kernel_launch(void* const* d_in, const int* in_sizes, int n_in,
                              void* d_out, int out_size)
{
    const float* h  = (const float*)d_in[0];
    const float* e  = (const float*)d_in[1];
    const int*   ei = (const int*)  d_in[2];
    const float* Wu = (const float*)d_in[3];
    const float* bu = (const float*)d_in[4];
    const float* Wv = (const float*)d_in[5];
    const float* bv = (const float*)d_in[6];
    const float* Wa = (const float*)d_in[7];
    const float* ba = (const float*)d_in[8];
    const float* Wb = (const float*)d_in[9];
    const float* bb = (const float*)d_in[10];
    const float* Wc = (const float*)d_in[11];
    const float* bc = (const float*)d_in[12];
    const float* gh = (const float*)d_in[13];
    const float* bh = (const float*)d_in[14];
    const float* ge = (const float*)d_in[15];
    const float* be = (const float*)d_in[16];

    const int V = in_sizes[0] / H_DIM;
    const int E = in_sizes[1] / H_DIM;

    float* h_out = (float*)d_out;
    float* e_out = (float*)d_out + (size_t)V * H_DIM;

    static int attr_set = 0;
    if (!attr_set) {
        cudaFuncSetAttribute(node_gemm_tc_kernel,
                             cudaFuncAttributeMaxDynamicSharedMemorySize, NG_SMEM_BYTES);
        cudaFuncSetAttribute(edge_gemm_kernel,
                             cudaFuncAttributeMaxDynamicSharedMemorySize, EG_SMEM_BYTES);
        attr_set = 1;
    }

    const int n4 = V * (H_DIM / 4);
    zero_agg_kernel<<<(n4 + 255) / 256, 256>>>(n4);
    cvt_weights_kernel<<<320, 256>>>(Wu, Wv, Wa, Wb, Wc);

    dim3 g1((V + 63) / 64, 4);
    node_gemm_tc_kernel<<<g1, 256, NG_SMEM_BYTES>>>(h, bu, bv, ba, bb, V);

    dim3 g2(2, E / 64);   // n-half fastest: sibling blocks share A rows in L2
    edge_gemm_kernel<<<g2, 256, EG_SMEM_BYTES>>>(e, E);

    edge_epilogue_kernel<<<E / 8, 256>>>(e, ei, bc, ge, be, e_out, E);

    node_epilogue_kernel<<<(V + 7) / 8, 256>>>(h, gh, bh, h_out, V);
}

// round 10
// speedup vs baseline: 1.1893x; 1.1197x over previous
#include <cuda_runtime.h>
#include <cstdint>
#include <cstddef>
#include <math.h>

#define H_DIM 256
#define MAXV 10000
#define MAXE 160000
#define LN_EPS 1e-5f

__device__ float g_nodebuf[(size_t)MAXV * 1024];   // [Uh | Vh | Ah | Bh]
__device__ float g_agg[(size_t)MAXV * H_DIM];
__device__ float g_ce[(size_t)MAXE * H_DIM];
__device__ float g_wtf[5 * 65536];                 // tf32 [Wu|Wv|Wa|Wb|Wc]

__device__ __forceinline__ void red_add_v4(float* addr, float a, float b, float c, float d) {
    asm volatile("red.global.add.v4.f32 [%0], {%1,%2,%3,%4};"
                 :: "l"(addr), "f"(a), "f"(b), "f"(c), "f"(d));
}

__device__ __forceinline__ float to_tf32(float x) {
    float y;
    asm("cvt.rna.tf32.f32 %0, %1;" : "=f"(y) : "f"(x));
    return y;
}

__device__ __forceinline__ float4 tf32_4(float4 v) {
    return make_float4(to_tf32(v.x), to_tf32(v.y), to_tf32(v.z), to_tf32(v.w));
}

__device__ __forceinline__ void mma_tf32(float& d0, float& d1, float& d2, float& d3,
                                         float a0, float a1, float a2, float a3,
                                         float b0, float b1) {
    asm volatile(
        "mma.sync.aligned.m16n8k8.row.col.f32.tf32.tf32.f32 "
        "{%0,%1,%2,%3}, {%4,%5,%6,%7}, {%8,%9}, {%0,%1,%2,%3};\n"
        : "+f"(d0), "+f"(d1), "+f"(d2), "+f"(d3)
        : "r"(__float_as_uint(a0)), "r"(__float_as_uint(a1)),
          "r"(__float_as_uint(a2)), "r"(__float_as_uint(a3)),
          "r"(__float_as_uint(b0)), "r"(__float_as_uint(b1)));
}

__device__ __forceinline__ void cpa16(uint32_t saddr, const void* g) {
    asm volatile("cp.async.cg.shared.global [%0], [%1], 16;" :: "r"(saddr), "l"(g));
}
__device__ __forceinline__ void cpa_commit() {
    asm volatile("cp.async.commit_group;");
}
template <int N>
__device__ __forceinline__ void cpa_wait() {
    asm volatile("cp.async.wait_group %0;" :: "n"(N));
}

#define SA_STRIDE 36    // fragment bank = (4g+t+kb)%32: conflict-free
#define SB_STRIDE 36
#define EB_STRIDE 260   // persistent B rows: 260%32=4 -> same permutation

// ---------------------------------------------------------------------------
// Kernel 0a: zero agg
// ---------------------------------------------------------------------------
__global__ void zero_agg_kernel(int n4) {
    int i = blockIdx.x * blockDim.x + threadIdx.x;
    if (i < n4) reinterpret_cast<float4*>(g_agg)[i] = make_float4(0.f, 0.f, 0.f, 0.f);
}

// ---------------------------------------------------------------------------
// Kernel 0b: pre-round weights to tf32
// ---------------------------------------------------------------------------
__global__ void cvt_weights_kernel(
    const float* __restrict__ Wu, const float* __restrict__ Wv,
    const float* __restrict__ Wa, const float* __restrict__ Wb,
    const float* __restrict__ Wc)
{
    int i = blockIdx.x * blockDim.x + threadIdx.x;
    int m = i >> 14;
    int r = i & 16383;
    const float* src = (m == 0) ? Wu : (m == 1) ? Wv : (m == 2) ? Wa : (m == 3) ? Wb : Wc;
    float4 v = __ldg(reinterpret_cast<const float4*>(src) + r);
    reinterpret_cast<float4*>(g_wtf)[i] = tf32_4(v);
}

// ---------------------------------------------------------------------------
// Kernel 1: node GEMM (R7 structure, 2 CTAs/SM)
// ---------------------------------------------------------------------------
#define NG_SA0 0
#define NG_SA1 2304
#define NG_SB0 4608
#define NG_SB1 13824
#define NG_SMEM_BYTES 92160

__global__ __launch_bounds__(256, 2) void node_gemm_tc_kernel(
    const float* __restrict__ h,
    const float* __restrict__ bu, const float* __restrict__ bv,
    const float* __restrict__ ba, const float* __restrict__ bb,
    int V)
{
    extern __shared__ float smem[];
    const uint32_t smem_u32 = (uint32_t)__cvta_generic_to_shared(smem);

    const int by = blockIdx.y;
    const float* W = g_wtf + (size_t)by * 65536;
    const float* bias = (by == 0) ? bu : (by == 1) ? bv : (by == 2) ? ba : bb;

    const int tid  = threadIdx.x;
    const int w    = tid >> 5;
    const int lane = tid & 31;
    const int g    = lane >> 2;
    const int t    = lane & 3;
    const int row0 = blockIdx.x * 64;

    const int lr  = tid >> 2;
    const int lk8 = (tid & 3) * 8;

    int gr = row0 + lr; if (gr >= V) gr = V - 1;
    const float* arow = h + (size_t)gr * H_DIM + lk8;
    const float* brow = W + (size_t)tid * H_DIM;

    const uint32_t sa_a[2] = { smem_u32 + (NG_SA0 + lr * SA_STRIDE + lk8) * 4,
                               smem_u32 + (NG_SA1 + lr * SA_STRIDE + lk8) * 4 };
    const uint32_t sb_a[2] = { smem_u32 + (NG_SB0 + tid * SB_STRIDE) * 4,
                               smem_u32 + (NG_SB1 + tid * SB_STRIDE) * 4 };

    float acc[4][4][4];
    #pragma unroll
    for (int mt = 0; mt < 4; mt++)
        #pragma unroll
        for (int nt = 0; nt < 4; nt++)
            #pragma unroll
            for (int q = 0; q < 4; q++) acc[mt][nt][q] = 0.f;

    cpa16(sa_a[0],      arow);
    cpa16(sa_a[0] + 16, arow + 4);
    #pragma unroll
    for (int q = 0; q < 8; q++) cpa16(sb_a[0] + q * 16, brow + q * 4);
    cpa_commit();

    #pragma unroll
    for (int c = 0; c < 8; c++) {
        const int buf = c & 1;
        if (c < 7) {
            const int nbuf = buf ^ 1;
            const int kk = (c + 1) * 32;
            cpa16(sa_a[nbuf],      arow + kk);
            cpa16(sa_a[nbuf] + 16, arow + kk + 4);
            #pragma unroll
            for (int q = 0; q < 8; q++) cpa16(sb_a[nbuf] + q * 16, brow + kk + q * 4);
            cpa_commit();
            cpa_wait<1>();
        } else {
            cpa_wait<0>();
        }
        __syncthreads();

        const float* sA = smem + (buf ? NG_SA1 : NG_SA0);
        const float* sB = smem + (buf ? NG_SB1 : NG_SB0);
        #pragma unroll
        for (int ks = 0; ks < 4; ks++) {
            const int kb = ks * 8;
            float bf[4][2];
            #pragma unroll
            for (int nt = 0; nt < 4; nt++) {
                int n = w * 32 + nt * 8 + g;
                bf[nt][0] = sB[n * SB_STRIDE + kb + t];
                bf[nt][1] = sB[n * SB_STRIDE + kb + t + 4];
            }
            #pragma unroll
            for (int mt = 0; mt < 4; mt++) {
                int m = mt * 16;
                float a0 = sA[(m + g) * SA_STRIDE + kb + t];
                float a1 = sA[(m + g + 8) * SA_STRIDE + kb + t];
                float a2 = sA[(m + g) * SA_STRIDE + kb + t + 4];
                float a3 = sA[(m + g + 8) * SA_STRIDE + kb + t + 4];
                #pragma unroll
                for (int nt = 0; nt < 4; nt++)
                    mma_tf32(acc[mt][nt][0], acc[mt][nt][1], acc[mt][nt][2], acc[mt][nt][3],
                             a0, a1, a2, a3, bf[nt][0], bf[nt][1]);
            }
        }
        __syncthreads();
    }

    #pragma unroll
    for (int mt = 0; mt < 4; mt++) {
        #pragma unroll
        for (int nt = 0; nt < 4; nt++) {
            int cc = w * 32 + nt * 8 + 2 * t;
            int r0 = row0 + mt * 16 + g;
            int r1 = r0 + 8;
            if (r0 < V) {
                float* o = g_nodebuf + (size_t)r0 * 1024 + by * 256 + cc;
                o[0] = acc[mt][nt][0] + bias[cc];
                o[1] = acc[mt][nt][1] + bias[cc + 1];
            }
            if (r1 < V) {
                float* o = g_nodebuf + (size_t)r1 * 1024 + by * 256 + cc;
                o[0] = acc[mt][nt][2] + bias[cc];
                o[1] = acc[mt][nt][3] + bias[cc + 1];
            }
        }
    }
}

// ---------------------------------------------------------------------------
// Kernel 2a: persistent-B edge GEMM.
// grid (2, 74): one CTA per SM; each block loads its 128-col Wc half into
// smem ONCE (rows stride 260 -> conflict-free fragment reads), then
// grid-strides over 64-edge tiles with a triple-buffered cp.async A pipeline.
// smem floats: B[128*260=33280] + A[3 * 2304] = 40192 floats = 160768 B.
// ---------------------------------------------------------------------------
#define EG_B_OFF 0
#define EG_A_OFF 33280
#define EG_A_BUF 2304
#define EG_SMEM_BYTES 160768

__global__ __launch_bounds__(256) void edge_gemm_kernel(
    const float* __restrict__ e, int E)
{
    extern __shared__ float smem[];
    const uint32_t smem_u32 = (uint32_t)__cvta_generic_to_shared(smem);

    const int nb = blockIdx.x;                 // 128-col half of Wc
    const int tid  = threadIdx.x;
    const int w    = tid >> 5;
    const int lane = tid & 31;
    const int g    = lane >> 2;
    const int t    = lane & 3;
    const int wm   = w >> 2;                   // rows wm*32
    const int wn   = w & 3;                    // cols wn*32

    const int lr  = tid >> 2;                  // A staging row 0..63
    const int lk8 = (tid & 3) * 8;

    const int nTiles = E / 64;

    // ---- load persistent B half: 128 rows x 256 k ----
    {
        const float* Wcv = g_wtf + 4 * 65536 + (size_t)(nb * 128) * H_DIM;
        #pragma unroll
        for (int i = 0; i < 32; i++) {
            int fi = tid + i * 256;            // float4 index 0..8191
            int n  = fi >> 6;
            int q  = fi & 63;
            cpa16(smem_u32 + (EG_B_OFF + n * EB_STRIDE + q * 4) * 4,
                  Wcv + (size_t)n * H_DIM + q * 4);
        }
        cpa_commit();                          // group: B
    }

    const uint32_t sa_a[3] = {
        smem_u32 + (EG_A_OFF + 0 * EG_A_BUF + lr * SA_STRIDE + lk8) * 4,
        smem_u32 + (EG_A_OFF + 1 * EG_A_BUF + lr * SA_STRIDE + lk8) * 4,
        smem_u32 + (EG_A_OFF + 2 * EG_A_BUF + lr * SA_STRIDE + lk8) * 4 };
    const float* sB = smem + EG_B_OFF;

    for (int ti = blockIdx.y; ti < nTiles; ti += 74) {
        const int e0 = ti * 64;
        const float* arow = e + (size_t)(e0 + lr) * H_DIM + lk8;

        float acc[2][4][4];
        #pragma unroll
        for (int mt = 0; mt < 2; mt++)
            #pragma unroll
            for (int nt = 0; nt < 4; nt++)
                #pragma unroll
                for (int q = 0; q < 4; q++) acc[mt][nt][q] = 0.f;

        // prologue: chunks 0,1 in flight
        cpa16(sa_a[0],      arow);
        cpa16(sa_a[0] + 16, arow + 4);
        cpa_commit();
        cpa16(sa_a[1],      arow + 32);
        cpa16(sa_a[1] + 16, arow + 36);
        cpa_commit();

        #pragma unroll
        for (int c = 0; c < 8; c++) {
            if (c < 6) {
                const int nbuf = (c + 2) % 3;
                const int kk = (c + 2) * 32;
                cpa16(sa_a[nbuf],      arow + kk);
                cpa16(sa_a[nbuf] + 16, arow + kk + 4);
                cpa_commit();
                cpa_wait<2>();
            } else if (c == 6) {
                cpa_wait<1>();
            } else {
                cpa_wait<0>();
            }
            __syncthreads();

            const float* sA = smem + EG_A_OFF + (c % 3) * EG_A_BUF;
            const int kg = c * 32;             // global k base for B
            #pragma unroll
            for (int ks = 0; ks < 4; ks++) {
                const int kb = ks * 8;
                float bf[4][2];
                #pragma unroll
                for (int nt = 0; nt < 4; nt++) {
                    int n = wn * 32 + nt * 8 + g;
                    bf[nt][0] = sB[n * EB_STRIDE + kg + kb + t];
                    bf[nt][1] = sB[n * EB_STRIDE + kg + kb + t + 4];
                }
                #pragma unroll
                for (int mt = 0; mt < 2; mt++) {
                    int m = wm * 32 + mt * 16;
                    float a0 = sA[(m + g) * SA_STRIDE + kb + t];
                    float a1 = sA[(m + g + 8) * SA_STRIDE + kb + t];
                    float a2 = sA[(m + g) * SA_STRIDE + kb + t + 4];
                    float a3 = sA[(m + g + 8) * SA_STRIDE + kb + t + 4];
                    #pragma unroll
                    for (int nt = 0; nt < 4; nt++)
                        mma_tf32(acc[mt][nt][0], acc[mt][nt][1], acc[mt][nt][2], acc[mt][nt][3],
                                 a0, a1, a2, a3, bf[nt][0], bf[nt][1]);
                }
            }
            __syncthreads();
        }

        // store Ce tile (streaming)
        #pragma unroll
        for (int mt = 0; mt < 2; mt++) {
            #pragma unroll
            for (int nt = 0; nt < 4; nt++) {
                int col = nb * 128 + wn * 32 + nt * 8 + 2 * t;
                int r0 = wm * 32 + mt * 16 + g;
                float* o0 = g_ce + (size_t)(e0 + r0) * H_DIM + col;
                float* o1 = g_ce + (size_t)(e0 + r0 + 8) * H_DIM + col;
                __stcs(reinterpret_cast<float2*>(o0), make_float2(acc[mt][nt][0], acc[mt][nt][1]));
                __stcs(reinterpret_cast<float2*>(o1), make_float2(acc[mt][nt][2], acc[mt][nt][3]));
            }
        }
    }
}

// ---------------------------------------------------------------------------
// Kernel 2b: edge epilogue (one warp per edge; high occupancy)
// ---------------------------------------------------------------------------
__global__ __launch_bounds__(256) void edge_epilogue_kernel(
    const float* __restrict__ e,
    const int*   __restrict__ ei,
    const float* __restrict__ bc,
    const float* __restrict__ ge, const float* __restrict__ be,
    float* __restrict__ e_out,
    int E)
{
    __shared__ float sBc[256], sGe[256], sBe[256];
    const int tid = threadIdx.x;
    sBc[tid] = bc[tid]; sGe[tid] = ge[tid]; sBe[tid] = be[tid];
    __syncthreads();

    const int warp = tid >> 5;
    const int lane = tid & 31;
    const int col0 = lane * 8;
    const int er = blockIdx.x * 8 + warp;

    const int s = __ldg(ei + er);
    const int d = __ldg(ei + E + er);

    const float4* cep = reinterpret_cast<const float4*>(g_ce + (size_t)er * H_DIM + col0);
    const float4* ah = reinterpret_cast<const float4*>(g_nodebuf + (size_t)d * 1024 + 512 + col0);
    const float4* bh = reinterpret_cast<const float4*>(g_nodebuf + (size_t)s * 1024 + 768 + col0);
    const float4* vh = reinterpret_cast<const float4*>(g_nodebuf + (size_t)d * 1024 + 256 + col0);
    const float4* erp = reinterpret_cast<const float4*>(e + (size_t)er * H_DIM + col0);

    float4 c0 = __ldcs(cep), c1 = __ldcs(cep + 1);
    float4 a0 = __ldg(ah),   a1 = __ldg(ah + 1);
    float4 b0 = __ldg(bh),   b1 = __ldg(bh + 1);
    float4 v0 = __ldg(vh),   v1 = __ldg(vh + 1);
    float4 r0 = __ldcs(erp), r1 = __ldcs(erp + 1);

    float x[8], vhv[8], erv[8];
    x[0] = c0.x + a0.x + b0.x; x[1] = c0.y + a0.y + b0.y;
    x[2] = c0.z + a0.z + b0.z; x[3] = c0.w + a0.w + b0.w;
    x[4] = c1.x + a1.x + b1.x; x[5] = c1.y + a1.y + b1.y;
    x[6] = c1.z + a1.z + b1.z; x[7] = c1.w + a1.w + b1.w;
    vhv[0] = v0.x; vhv[1] = v0.y; vhv[2] = v0.z; vhv[3] = v0.w;
    vhv[4] = v1.x; vhv[5] = v1.y; vhv[6] = v1.z; vhv[7] = v1.w;
    erv[0] = r0.x; erv[1] = r0.y; erv[2] = r0.z; erv[3] = r0.w;
    erv[4] = r1.x; erv[5] = r1.y; erv[6] = r1.z; erv[7] = r1.w;

    float sum = 0.f, sq = 0.f;
    #pragma unroll
    for (int c = 0; c < 8; c++) {
        float xv = x[c] + sBc[col0 + c];
        x[c] = xv;
        sum += xv;
        sq  += xv * xv;
    }

    float gv[8];
    #pragma unroll
    for (int c = 0; c < 8; c++) {
        float gt = 1.f / (1.f + __expf(-x[c]));
        gv[c] = gt * vhv[c];
    }
    float* ag = g_agg + (size_t)s * H_DIM + col0;
    red_add_v4(ag,     gv[0], gv[1], gv[2], gv[3]);
    red_add_v4(ag + 4, gv[4], gv[5], gv[6], gv[7]);

    #pragma unroll
    for (int off = 16; off > 0; off >>= 1) {
        sum += __shfl_xor_sync(0xFFFFFFFFu, sum, off);
        sq  += __shfl_xor_sync(0xFFFFFFFFu, sq,  off);
    }
    const float mu  = sum * (1.f / 256.f);
    const float var = sq * (1.f / 256.f) - mu * mu;
    const float rs  = rsqrtf(var + LN_EPS);

    float4 o0, o1;
    float* ov0 = &o0.x; float* ov1 = &o1.x;
    #pragma unroll
    for (int c = 0; c < 4; c++) {
        float y = (x[c] - mu) * rs * sGe[col0 + c] + sBe[col0 + c];
        y = y > 0.f ? y : 0.f;
        ov0[c] = erv[c] + y;
    }
    #pragma unroll
    for (int c = 0; c < 4; c++) {
        float y = (x[c + 4] - mu) * rs * sGe[col0 + c + 4] + sBe[col0 + c + 4];
        y = y > 0.f ? y : 0.f;
        ov1[c] = erv[c + 4] + y;
    }
    float4* orow = reinterpret_cast<float4*>(e_out + (size_t)er * H_DIM + col0);
    __stcs(orow, o0);
    __stcs(orow + 1, o1);
}

// ---------------------------------------------------------------------------
// Kernel 3: node epilogue
// ---------------------------------------------------------------------------
__global__ __launch_bounds__(256) void node_epilogue_kernel(
    const float* __restrict__ h,
    const float* __restrict__ gh, const float* __restrict__ bhv,
    float* __restrict__ h_out, int V)
{
    const int warp = threadIdx.x >> 5;
    const int lane = threadIdx.x & 31;
    const int n = blockIdx.x * 8 + warp;
    if (n >= V) return;
    const int col0 = lane * 8;

    const float4* u  = reinterpret_cast<const float4*>(g_nodebuf + (size_t)n * 1024 + col0);
    const float4* ag = reinterpret_cast<const float4*>(g_agg     + (size_t)n * H_DIM + col0);
    const float4* hr = reinterpret_cast<const float4*>(h         + (size_t)n * H_DIM + col0);

    float4 u0 = __ldcs(u),  u1 = __ldcs(u + 1);
    float4 g0 = __ldcs(ag), g1 = __ldcs(ag + 1);
    float4 h0 = __ldcs(hr), h1 = __ldcs(hr + 1);

    float x[8], hv[8];
    x[0] = u0.x + g0.x; x[1] = u0.y + g0.y; x[2] = u0.z + g0.z; x[3] = u0.w + g0.w;
    x[4] = u1.x + g1.x; x[5] = u1.y + g1.y; x[6] = u1.z + g1.z; x[7] = u1.w + g1.w;
    hv[0] = h0.x; hv[1] = h0.y; hv[2] = h0.z; hv[3] = h0.w;
    hv[4] = h1.x; hv[5] = h1.y; hv[6] = h1.z; hv[7] = h1.w;

    float sum = 0.f, sq = 0.f;
    #pragma unroll
    for (int c = 0; c < 8; c++) { sum += x[c]; sq += x[c] * x[c]; }
    #pragma unroll
    for (int off = 16; off > 0; off >>= 1) {
        sum += __shfl_xor_sync(0xFFFFFFFFu, sum, off);
        sq  += __shfl_xor_sync(0xFFFFFFFFu, sq,  off);
    }
    const float mu  = sum * (1.f / 256.f);
    const float var = sq * (1.f / 256.f) - mu * mu;
    const float rs  = rsqrtf(var + LN_EPS);

    float4 o0, o1;
    float* ov0 = &o0.x; float* ov1 = &o1.x;
    #pragma unroll
    for (int c = 0; c < 4; c++) {
        float y = (x[c] - mu) * rs * gh[col0 + c] + bhv[col0 + c];
        y = y > 0.f ? y : 0.f;
        ov0[c] = hv[c] + y;
    }
    #pragma unroll
    for (int c = 0; c < 4; c++) {
        float y = (x[c + 4] - mu) * rs * gh[col0 + c + 4] + bhv[col0 + c + 4];
        y = y > 0.f ? y : 0.f;
        ov1[c] = hv[c + 4] + y;
    }
    float4* o = reinterpret_cast<float4*>(h_out + (size_t)n * H_DIM + col0);
    __stcs(o, o0);
    __stcs(o + 1, o1);
}

// ---------------------------------------------------------------------------
extern "C" void kernel_launch(void* const* d_in, const int* in_sizes, int n_in,
                              void* d_out, int out_size)
{
    const float* h  = (const float*)d_in[0];
    const float* e  = (const float*)d_in[1];
    const int*   ei = (const int*)  d_in[2];
    const float* Wu = (const float*)d_in[3];
    const float* bu = (const float*)d_in[4];
    const float* Wv = (const float*)d_in[5];
    const float* bv = (const float*)d_in[6];
    const float* Wa = (const float*)d_in[7];
    const float* ba = (const float*)d_in[8];
    const float* Wb = (const float*)d_in[9];
    const float* bb = (const float*)d_in[10];
    const float* Wc = (const float*)d_in[11];
    const float* bc = (const float*)d_in[12];
    const float* gh = (const float*)d_in[13];
    const float* bh = (const float*)d_in[14];
    const float* ge = (const float*)d_in[15];
    const float* be = (const float*)d_in[16];

    const int V = in_sizes[0] / H_DIM;
    const int E = in_sizes[1] / H_DIM;

    float* h_out = (float*)d_out;
    float* e_out = (float*)d_out + (size_t)V * H_DIM;

    static int attr_set = 0;
    if (!attr_set) {
        cudaFuncSetAttribute(node_gemm_tc_kernel,
                             cudaFuncAttributeMaxDynamicSharedMemorySize, NG_SMEM_BYTES);
        cudaFuncSetAttribute(edge_gemm_kernel,
                             cudaFuncAttributeMaxDynamicSharedMemorySize, EG_SMEM_BYTES);
        attr_set = 1;
    }

    const int n4 = V * (H_DIM / 4);
    zero_agg_kernel<<<(n4 + 255) / 256, 256>>>(n4);
    cvt_weights_kernel<<<320, 256>>>(Wu, Wv, Wa, Wb, Wc);

    dim3 g1((V + 63) / 64, 4);
    node_gemm_tc_kernel<<<g1, 256, NG_SMEM_BYTES>>>(h, bu, bv, ba, bb, V);

    dim3 g2(2, 74);   // persistent: one CTA per SM, B loaded once per block
    edge_gemm_kernel<<<g2, 256, EG_SMEM_BYTES>>>(e, E);

    edge_epilogue_kernel<<<E / 8, 256>>>(e, ei, bc, ge, be, e_out, E);

    node_epilogue_kernel<<<(V + 7) / 8, 256>>>(h, gh, bh, h_out, V);
}

// round 11
// speedup vs baseline: 1.2771x; 1.0738x over previous
#include <cuda_runtime.h>
#include <cstdint>
#include <cstddef>
#include <math.h>

#define H_DIM 256
#define MAXV 10000
#define MAXE 160000
#define LN_EPS 1e-5f

__device__ float g_nodebuf[(size_t)MAXV * 1024];   // [Uh | Vh | Ah | Bh]
__device__ float g_agg[(size_t)MAXV * H_DIM];
__device__ float g_ce[(size_t)MAXE * H_DIM];
__device__ float g_wtf[5 * 65536];                 // tf32 [Wu|Wv|Wa|Wb|Wc]

__device__ __forceinline__ void red_add_v4(float* addr, float a, float b, float c, float d) {
    asm volatile("red.global.add.v4.f32 [%0], {%1,%2,%3,%4};"
                 :: "l"(addr), "f"(a), "f"(b), "f"(c), "f"(d));
}

__device__ __forceinline__ float to_tf32(float x) {
    float y;
    asm("cvt.rna.tf32.f32 %0, %1;" : "=f"(y) : "f"(x));
    return y;
}

__device__ __forceinline__ float4 tf32_4(float4 v) {
    return make_float4(to_tf32(v.x), to_tf32(v.y), to_tf32(v.z), to_tf32(v.w));
}

__device__ __forceinline__ void mma_tf32(float& d0, float& d1, float& d2, float& d3,
                                         float a0, float a1, float a2, float a3,
                                         float b0, float b1) {
    asm volatile(
        "mma.sync.aligned.m16n8k8.row.col.f32.tf32.tf32.f32 "
        "{%0,%1,%2,%3}, {%4,%5,%6,%7}, {%8,%9}, {%0,%1,%2,%3};\n"
        : "+f"(d0), "+f"(d1), "+f"(d2), "+f"(d3)
        : "r"(__float_as_uint(a0)), "r"(__float_as_uint(a1)),
          "r"(__float_as_uint(a2)), "r"(__float_as_uint(a3)),
          "r"(__float_as_uint(b0)), "r"(__float_as_uint(b1)));
}

__device__ __forceinline__ void cpa16(uint32_t saddr, const void* g) {
    asm volatile("cp.async.cg.shared.global [%0], [%1], 16;" :: "r"(saddr), "l"(g));
}
__device__ __forceinline__ void cpa_commit() {
    asm volatile("cp.async.commit_group;");
}
template <int N>
__device__ __forceinline__ void cpa_wait() {
    asm volatile("cp.async.wait_group %0;" :: "n"(N));
}

#define SA_STRIDE 36    // fragment bank = (4g+t+kb)%32: conflict-free
#define SB_STRIDE 36
#define EB_STRIDE 260   // persistent B rows: 260%32=4 -> same permutation

// ---------------------------------------------------------------------------
// Kernel 0a: zero agg
// ---------------------------------------------------------------------------
__global__ void zero_agg_kernel(int n4) {
    int i = blockIdx.x * blockDim.x + threadIdx.x;
    if (i < n4) reinterpret_cast<float4*>(g_agg)[i] = make_float4(0.f, 0.f, 0.f, 0.f);
}

// ---------------------------------------------------------------------------
// Kernel 0b: pre-round weights to tf32
// ---------------------------------------------------------------------------
__global__ void cvt_weights_kernel(
    const float* __restrict__ Wu, const float* __restrict__ Wv,
    const float* __restrict__ Wa, const float* __restrict__ Wb,
    const float* __restrict__ Wc)
{
    int i = blockIdx.x * blockDim.x + threadIdx.x;
    int m = i >> 14;
    int r = i & 16383;
    const float* src = (m == 0) ? Wu : (m == 1) ? Wv : (m == 2) ? Wa : (m == 3) ? Wb : Wc;
    float4 v = __ldg(reinterpret_cast<const float4*>(src) + r);
    reinterpret_cast<float4*>(g_wtf)[i] = tf32_4(v);
}

// ---------------------------------------------------------------------------
// Kernel 1: node GEMM (R7 structure, 2 CTAs/SM)
// ---------------------------------------------------------------------------
#define NG_SA0 0
#define NG_SA1 2304
#define NG_SB0 4608
#define NG_SB1 13824
#define NG_SMEM_BYTES 92160

__global__ __launch_bounds__(256, 2) void node_gemm_tc_kernel(
    const float* __restrict__ h,
    const float* __restrict__ bu, const float* __restrict__ bv,
    const float* __restrict__ ba, const float* __restrict__ bb,
    int V)
{
    extern __shared__ float smem[];
    const uint32_t smem_u32 = (uint32_t)__cvta_generic_to_shared(smem);

    const int by = blockIdx.y;
    const float* W = g_wtf + (size_t)by * 65536;
    const float* bias = (by == 0) ? bu : (by == 1) ? bv : (by == 2) ? ba : bb;

    const int tid  = threadIdx.x;
    const int w    = tid >> 5;
    const int lane = tid & 31;
    const int g    = lane >> 2;
    const int t    = lane & 3;
    const int row0 = blockIdx.x * 64;

    const int lr  = tid >> 2;
    const int lk8 = (tid & 3) * 8;

    int gr = row0 + lr; if (gr >= V) gr = V - 1;
    const float* arow = h + (size_t)gr * H_DIM + lk8;
    const float* brow = W + (size_t)tid * H_DIM;

    const uint32_t sa_a[2] = { smem_u32 + (NG_SA0 + lr * SA_STRIDE + lk8) * 4,
                               smem_u32 + (NG_SA1 + lr * SA_STRIDE + lk8) * 4 };
    const uint32_t sb_a[2] = { smem_u32 + (NG_SB0 + tid * SB_STRIDE) * 4,
                               smem_u32 + (NG_SB1 + tid * SB_STRIDE) * 4 };

    float acc[4][4][4];
    #pragma unroll
    for (int mt = 0; mt < 4; mt++)
        #pragma unroll
        for (int nt = 0; nt < 4; nt++)
            #pragma unroll
            for (int q = 0; q < 4; q++) acc[mt][nt][q] = 0.f;

    cpa16(sa_a[0],      arow);
    cpa16(sa_a[0] + 16, arow + 4);
    #pragma unroll
    for (int q = 0; q < 8; q++) cpa16(sb_a[0] + q * 16, brow + q * 4);
    cpa_commit();

    #pragma unroll
    for (int c = 0; c < 8; c++) {
        const int buf = c & 1;
        if (c < 7) {
            const int nbuf = buf ^ 1;
            const int kk = (c + 1) * 32;
            cpa16(sa_a[nbuf],      arow + kk);
            cpa16(sa_a[nbuf] + 16, arow + kk + 4);
            #pragma unroll
            for (int q = 0; q < 8; q++) cpa16(sb_a[nbuf] + q * 16, brow + kk + q * 4);
            cpa_commit();
            cpa_wait<1>();
        } else {
            cpa_wait<0>();
        }
        __syncthreads();

        const float* sA = smem + (buf ? NG_SA1 : NG_SA0);
        const float* sB = smem + (buf ? NG_SB1 : NG_SB0);
        #pragma unroll
        for (int ks = 0; ks < 4; ks++) {
            const int kb = ks * 8;
            float bf[4][2];
            #pragma unroll
            for (int nt = 0; nt < 4; nt++) {
                int n = w * 32 + nt * 8 + g;
                bf[nt][0] = sB[n * SB_STRIDE + kb + t];
                bf[nt][1] = sB[n * SB_STRIDE + kb + t + 4];
            }
            #pragma unroll
            for (int mt = 0; mt < 4; mt++) {
                int m = mt * 16;
                float a0 = sA[(m + g) * SA_STRIDE + kb + t];
                float a1 = sA[(m + g + 8) * SA_STRIDE + kb + t];
                float a2 = sA[(m + g) * SA_STRIDE + kb + t + 4];
                float a3 = sA[(m + g + 8) * SA_STRIDE + kb + t + 4];
                #pragma unroll
                for (int nt = 0; nt < 4; nt++)
                    mma_tf32(acc[mt][nt][0], acc[mt][nt][1], acc[mt][nt][2], acc[mt][nt][3],
                             a0, a1, a2, a3, bf[nt][0], bf[nt][1]);
            }
        }
        __syncthreads();
    }

    #pragma unroll
    for (int mt = 0; mt < 4; mt++) {
        #pragma unroll
        for (int nt = 0; nt < 4; nt++) {
            int cc = w * 32 + nt * 8 + 2 * t;
            int r0 = row0 + mt * 16 + g;
            int r1 = r0 + 8;
            if (r0 < V) {
                float* o = g_nodebuf + (size_t)r0 * 1024 + by * 256 + cc;
                o[0] = acc[mt][nt][0] + bias[cc];
                o[1] = acc[mt][nt][1] + bias[cc + 1];
            }
            if (r1 < V) {
                float* o = g_nodebuf + (size_t)r1 * 1024 + by * 256 + cc;
                o[0] = acc[mt][nt][2] + bias[cc];
                o[1] = acc[mt][nt][3] + bias[cc + 1];
            }
        }
    }
}

// ---------------------------------------------------------------------------
// Kernel 2a: persistent-B edge GEMM, 512 threads, 256x128 tile.
// grid (2, 74): 1 CTA/SM (16 warps). B half loaded once; A double-buffered.
// Warp grid 8m x 2n: warp = 32 rows x 64 cols, 64 accs/thread,
// LDS/MMA ratio 1.5 (vs 2.0 at 32x32).
// smem floats: B[128*260=33280] + A[2 * 256*36=9216] = 51712 -> 206848 B.
// ---------------------------------------------------------------------------
#define EG_B_OFF 0
#define EG_A_OFF 33280
#define EG_A_BUF 9216
#define EG_SMEM_BYTES 206848

__global__ __launch_bounds__(512, 1) void edge_gemm_kernel(
    const float* __restrict__ e, int E)
{
    extern __shared__ float smem[];
    const uint32_t smem_u32 = (uint32_t)__cvta_generic_to_shared(smem);

    const int nb = blockIdx.x;                 // 128-col half of Wc
    const int tid  = threadIdx.x;
    const int w    = tid >> 5;
    const int lane = tid & 31;
    const int g    = lane >> 2;
    const int t    = lane & 3;
    const int wm   = w >> 1;                   // 0..7 -> rows wm*32
    const int wn   = w & 1;                    // 0..1 -> cols wn*64

    // A staging: each thread stages 4 rows (r0 + i*64), 4 floats at aq
    const int ar0 = tid >> 3;                  // 0..63
    const int aq  = (tid & 7) * 4;             // 0..28

    const int nTiles = E / 256;                // 625

    // ---- persistent B half: 128 rows x 256 k ----
    {
        const float* Wcv = g_wtf + 4 * 65536 + (size_t)(nb * 128) * H_DIM;
        #pragma unroll
        for (int i = 0; i < 16; i++) {
            int fi = tid + i * 512;            // float4 index 0..8191
            int n  = fi >> 6;
            int q  = fi & 63;
            cpa16(smem_u32 + (EG_B_OFF + n * EB_STRIDE + q * 4) * 4,
                  Wcv + (size_t)n * H_DIM + q * 4);
        }
        cpa_commit();
    }

    const uint32_t sa_base[2] = {
        smem_u32 + (EG_A_OFF + 0 * EG_A_BUF + ar0 * SA_STRIDE + aq) * 4,
        smem_u32 + (EG_A_OFF + 1 * EG_A_BUF + ar0 * SA_STRIDE + aq) * 4 };
    const float* sB = smem + EG_B_OFF;

    for (int ti = blockIdx.y; ti < nTiles; ti += 74) {
        const int e0 = ti * 256;
        const float* abase = e + (size_t)(e0 + ar0) * H_DIM + aq;

        float acc[2][8][4];
        #pragma unroll
        for (int mt = 0; mt < 2; mt++)
            #pragma unroll
            for (int nt = 0; nt < 8; nt++)
                #pragma unroll
                for (int q = 0; q < 4; q++) acc[mt][nt][q] = 0.f;

        // prologue: chunk 0 -> buf 0
        #pragma unroll
        for (int i = 0; i < 4; i++)
            cpa16(sa_base[0] + i * 64 * SA_STRIDE * 4, abase + (size_t)i * 64 * H_DIM);
        cpa_commit();

        #pragma unroll
        for (int c = 0; c < 8; c++) {
            if (c < 7) {
                const int nbuf = (c + 1) & 1;
                const int kk = (c + 1) * 32;
                #pragma unroll
                for (int i = 0; i < 4; i++)
                    cpa16(sa_base[nbuf] + i * 64 * SA_STRIDE * 4,
                          abase + (size_t)i * 64 * H_DIM + kk);
                cpa_commit();
                cpa_wait<1>();
            } else {
                cpa_wait<0>();
            }
            __syncthreads();

            const float* sA = smem + EG_A_OFF + (c & 1) * EG_A_BUF;
            const int kg = c * 32;
            #pragma unroll
            for (int ks = 0; ks < 4; ks++) {
                const int kb = ks * 8;
                float bf[8][2];
                #pragma unroll
                for (int nt = 0; nt < 8; nt++) {
                    int n = wn * 64 + nt * 8 + g;
                    bf[nt][0] = sB[n * EB_STRIDE + kg + kb + t];
                    bf[nt][1] = sB[n * EB_STRIDE + kg + kb + t + 4];
                }
                #pragma unroll
                for (int mt = 0; mt < 2; mt++) {
                    int m = wm * 32 + mt * 16;
                    float a0 = sA[(m + g) * SA_STRIDE + kb + t];
                    float a1 = sA[(m + g + 8) * SA_STRIDE + kb + t];
                    float a2 = sA[(m + g) * SA_STRIDE + kb + t + 4];
                    float a3 = sA[(m + g + 8) * SA_STRIDE + kb + t + 4];
                    #pragma unroll
                    for (int nt = 0; nt < 8; nt++)
                        mma_tf32(acc[mt][nt][0], acc[mt][nt][1], acc[mt][nt][2], acc[mt][nt][3],
                                 a0, a1, a2, a3, bf[nt][0], bf[nt][1]);
                }
            }
            __syncthreads();
        }

        // store Ce tile (streaming)
        #pragma unroll
        for (int mt = 0; mt < 2; mt++) {
            #pragma unroll
            for (int nt = 0; nt < 8; nt++) {
                int col = nb * 128 + wn * 64 + nt * 8 + 2 * t;
                int r0 = wm * 32 + mt * 16 + g;
                float* o0 = g_ce + (size_t)(e0 + r0) * H_DIM + col;
                float* o1 = g_ce + (size_t)(e0 + r0 + 8) * H_DIM + col;
                __stcs(reinterpret_cast<float2*>(o0), make_float2(acc[mt][nt][0], acc[mt][nt][1]));
                __stcs(reinterpret_cast<float2*>(o1), make_float2(acc[mt][nt][2], acc[mt][nt][3]));
            }
        }
    }
}

// ---------------------------------------------------------------------------
// Kernel 2b: edge epilogue (one warp per edge; high occupancy)
// ---------------------------------------------------------------------------
__global__ __launch_bounds__(256) void edge_epilogue_kernel(
    const float* __restrict__ e,
    const int*   __restrict__ ei,
    const float* __restrict__ bc,
    const float* __restrict__ ge, const float* __restrict__ be,
    float* __restrict__ e_out,
    int E)
{
    __shared__ float sBc[256], sGe[256], sBe[256];
    const int tid = threadIdx.x;
    sBc[tid] = bc[tid]; sGe[tid] = ge[tid]; sBe[tid] = be[tid];
    __syncthreads();

    const int warp = tid >> 5;
    const int lane = tid & 31;
    const int col0 = lane * 8;
    const int er = blockIdx.x * 8 + warp;

    const int s = __ldg(ei + er);
    const int d = __ldg(ei + E + er);

    const float4* cep = reinterpret_cast<const float4*>(g_ce + (size_t)er * H_DIM + col0);
    const float4* ah = reinterpret_cast<const float4*>(g_nodebuf + (size_t)d * 1024 + 512 + col0);
    const float4* bh = reinterpret_cast<const float4*>(g_nodebuf + (size_t)s * 1024 + 768 + col0);
    const float4* vh = reinterpret_cast<const float4*>(g_nodebuf + (size_t)d * 1024 + 256 + col0);
    const float4* erp = reinterpret_cast<const float4*>(e + (size_t)er * H_DIM + col0);

    float4 c0 = __ldcs(cep), c1 = __ldcs(cep + 1);
    float4 a0 = __ldg(ah),   a1 = __ldg(ah + 1);
    float4 b0 = __ldg(bh),   b1 = __ldg(bh + 1);
    float4 v0 = __ldg(vh),   v1 = __ldg(vh + 1);
    float4 r0 = __ldcs(erp), r1 = __ldcs(erp + 1);

    float x[8], vhv[8], erv[8];
    x[0] = c0.x + a0.x + b0.x; x[1] = c0.y + a0.y + b0.y;
    x[2] = c0.z + a0.z + b0.z; x[3] = c0.w + a0.w + b0.w;
    x[4] = c1.x + a1.x + b1.x; x[5] = c1.y + a1.y + b1.y;
    x[6] = c1.z + a1.z + b1.z; x[7] = c1.w + a1.w + b1.w;
    vhv[0] = v0.x; vhv[1] = v0.y; vhv[2] = v0.z; vhv[3] = v0.w;
    vhv[4] = v1.x; vhv[5] = v1.y; vhv[6] = v1.z; vhv[7] = v1.w;
    erv[0] = r0.x; erv[1] = r0.y; erv[2] = r0.z; erv[3] = r0.w;
    erv[4] = r1.x; erv[5] = r1.y; erv[6] = r1.z; erv[7] = r1.w;

    float sum = 0.f, sq = 0.f;
    #pragma unroll
    for (int c = 0; c < 8; c++) {
        float xv = x[c] + sBc[col0 + c];
        x[c] = xv;
        sum += xv;
        sq  += xv * xv;
    }

    float gv[8];
    #pragma unroll
    for (int c = 0; c < 8; c++) {
        float gt = 1.f / (1.f + __expf(-x[c]));
        gv[c] = gt * vhv[c];
    }
    float* ag = g_agg + (size_t)s * H_DIM + col0;
    red_add_v4(ag,     gv[0], gv[1], gv[2], gv[3]);
    red_add_v4(ag + 4, gv[4], gv[5], gv[6], gv[7]);

    #pragma unroll
    for (int off = 16; off > 0; off >>= 1) {
        sum += __shfl_xor_sync(0xFFFFFFFFu, sum, off);
        sq  += __shfl_xor_sync(0xFFFFFFFFu, sq,  off);
    }
    const float mu  = sum * (1.f / 256.f);
    const float var = sq * (1.f / 256.f) - mu * mu;
    const float rs  = rsqrtf(var + LN_EPS);

    float4 o0, o1;
    float* ov0 = &o0.x; float* ov1 = &o1.x;
    #pragma unroll
    for (int c = 0; c < 4; c++) {
        float y = (x[c] - mu) * rs * sGe[col0 + c] + sBe[col0 + c];
        y = y > 0.f ? y : 0.f;
        ov0[c] = erv[c] + y;
    }
    #pragma unroll
    for (int c = 0; c < 4; c++) {
        float y = (x[c + 4] - mu) * rs * sGe[col0 + c + 4] + sBe[col0 + c + 4];
        y = y > 0.f ? y : 0.f;
        ov1[c] = erv[c + 4] + y;
    }
    float4* orow = reinterpret_cast<float4*>(e_out + (size_t)er * H_DIM + col0);
    __stcs(orow, o0);
    __stcs(orow + 1, o1);
}

// ---------------------------------------------------------------------------
// Kernel 3: node epilogue
// ---------------------------------------------------------------------------
__global__ __launch_bounds__(256) void node_epilogue_kernel(
    const float* __restrict__ h,
    const float* __restrict__ gh, const float* __restrict__ bhv,
    float* __restrict__ h_out, int V)
{
    const int warp = threadIdx.x >> 5;
    const int lane = threadIdx.x & 31;
    const int n = blockIdx.x * 8 + warp;
    if (n >= V) return;
    const int col0 = lane * 8;

    const float4* u  = reinterpret_cast<const float4*>(g_nodebuf + (size_t)n * 1024 + col0);
    const float4* ag = reinterpret_cast<const float4*>(g_agg     + (size_t)n * H_DIM + col0);
    const float4* hr = reinterpret_cast<const float4*>(h         + (size_t)n * H_DIM + col0);

    float4 u0 = __ldcs(u),  u1 = __ldcs(u + 1);
    float4 g0 = __ldcs(ag), g1 = __ldcs(ag + 1);
    float4 h0 = __ldcs(hr), h1 = __ldcs(hr + 1);

    float x[8], hv[8];
    x[0] = u0.x + g0.x; x[1] = u0.y + g0.y; x[2] = u0.z + g0.z; x[3] = u0.w + g0.w;
    x[4] = u1.x + g1.x; x[5] = u1.y + g1.y; x[6] = u1.z + g1.z; x[7] = u1.w + g1.w;
    hv[0] = h0.x; hv[1] = h0.y; hv[2] = h0.z; hv[3] = h0.w;
    hv[4] = h1.x; hv[5] = h1.y; hv[6] = h1.z; hv[7] = h1.w;

    float sum = 0.f, sq = 0.f;
    #pragma unroll
    for (int c = 0; c < 8; c++) { sum += x[c]; sq += x[c] * x[c]; }
    #pragma unroll
    for (int off = 16; off > 0; off >>= 1) {
        sum += __shfl_xor_sync(0xFFFFFFFFu, sum, off);
        sq  += __shfl_xor_sync(0xFFFFFFFFu, sq,  off);
    }
    const float mu  = sum * (1.f / 256.f);
    const float var = sq * (1.f / 256.f) - mu * mu;
    const float rs  = rsqrtf(var + LN_EPS);

    float4 o0, o1;
    float* ov0 = &o0.x; float* ov1 = &o1.x;
    #pragma unroll
    for (int c = 0; c < 4; c++) {
        float y = (x[c] - mu) * rs * gh[col0 + c] + bhv[col0 + c];
        y = y > 0.f ? y : 0.f;
        ov0[c] = hv[c] + y;
    }
    #pragma unroll
    for (int c = 0; c < 4; c++) {
        float y = (x[c + 4] - mu) * rs * gh[col0 + c + 4] + bhv[col0 + c + 4];
        y = y > 0.f ? y : 0.f;
        ov1[c] = hv[c + 4] + y;
    }
    float4* o = reinterpret_cast<float4*>(h_out + (size_t)n * H_DIM + col0);
    __stcs(o, o0);
    __stcs(o + 1, o1);
}

// ---------------------------------------------------------------------------
extern "C" void kernel_launch(void* const* d_in, const int* in_sizes, int n_in,
                              void* d_out, int out_size)
{
    const float* h  = (const float*)d_in[0];
    const float* e  = (const float*)d_in[1];
    const int*   ei = (const int*)  d_in[2];
    const float* Wu = (const float*)d_in[3];
    const float* bu = (const float*)d_in[4];
    const float* Wv = (const float*)d_in[5];
    const float* bv = (const float*)d_in[6];
    const float* Wa = (const float*)d_in[7];
    const float* ba = (const float*)d_in[8];
    const float* Wb = (const float*)d_in[9];
    const float* bb = (const float*)d_in[10];
    const float* Wc = (const float*)d_in[11];
    const float* bc = (const float*)d_in[12];
    const float* gh = (const float*)d_in[13];
    const float* bh = (const float*)d_in[14];
    const float* ge = (const float*)d_in[15];
    const float* be = (const float*)d_in[16];

    const int V = in_sizes[0] / H_DIM;
    const int E = in_sizes[1] / H_DIM;

    float* h_out = (float*)d_out;
    float* e_out = (float*)d_out + (size_t)V * H_DIM;

    static int attr_set = 0;
    if (!attr_set) {
        cudaFuncSetAttribute(node_gemm_tc_kernel,
                             cudaFuncAttributeMaxDynamicSharedMemorySize, NG_SMEM_BYTES);
        cudaFuncSetAttribute(edge_gemm_kernel,
                             cudaFuncAttributeMaxDynamicSharedMemorySize, EG_SMEM_BYTES);
        attr_set = 1;
    }

    const int n4 = V * (H_DIM / 4);
    zero_agg_kernel<<<(n4 + 255) / 256, 256>>>(n4);
    cvt_weights_kernel<<<320, 256>>>(Wu, Wv, Wa, Wb, Wc);

    dim3 g1((V + 63) / 64, 4);
    node_gemm_tc_kernel<<<g1, 256, NG_SMEM_BYTES>>>(h, bu, bv, ba, bb, V);

    dim3 g2(2, 74);   // persistent: 1 CTA/SM, 16 warps, B loaded once
    edge_gemm_kernel<<<g2, 512, EG_SMEM_BYTES>>>(e, E);

    edge_epilogue_kernel<<<E / 8, 256>>>(e, ei, bc, ge, be, e_out, E);

    node_epilogue_kernel<<<(V + 7) / 8, 256>>>(h, gh, bh, h_out, V);
}

// round 12
// speedup vs baseline: 1.2914x; 1.0112x over previous
#include <cuda_runtime.h>
#include <cstdint>
#include <cstddef>
#include <math.h>

#define H_DIM 256
#define MAXV 10000
#define MAXE 160000
#define LN_EPS 1e-5f

__device__ float g_nodebuf[(size_t)MAXV * 1024];   // [ -- | Vh | Ah | Bh]
__device__ float g_agg[(size_t)MAXV * H_DIM];      // Uh+bias, then += gated agg
__device__ float g_ce[(size_t)MAXE * H_DIM];
__device__ float g_wtf[5 * 65536];                 // tf32 [Wu|Wv|Wa|Wb|Wc]
__device__ int   g_tile_ctr[2];                    // work-steal counters per half

__device__ __forceinline__ void red_add_v4(float* addr, float a, float b, float c, float d) {
    asm volatile("red.global.add.v4.f32 [%0], {%1,%2,%3,%4};"
                 :: "l"(addr), "f"(a), "f"(b), "f"(c), "f"(d));
}

__device__ __forceinline__ float to_tf32(float x) {
    float y;
    asm("cvt.rna.tf32.f32 %0, %1;" : "=f"(y) : "f"(x));
    return y;
}

__device__ __forceinline__ float4 tf32_4(float4 v) {
    return make_float4(to_tf32(v.x), to_tf32(v.y), to_tf32(v.z), to_tf32(v.w));
}

__device__ __forceinline__ void mma_tf32(float& d0, float& d1, float& d2, float& d3,
                                         float a0, float a1, float a2, float a3,
                                         float b0, float b1) {
    asm volatile(
        "mma.sync.aligned.m16n8k8.row.col.f32.tf32.tf32.f32 "
        "{%0,%1,%2,%3}, {%4,%5,%6,%7}, {%8,%9}, {%0,%1,%2,%3};\n"
        : "+f"(d0), "+f"(d1), "+f"(d2), "+f"(d3)
        : "r"(__float_as_uint(a0)), "r"(__float_as_uint(a1)),
          "r"(__float_as_uint(a2)), "r"(__float_as_uint(a3)),
          "r"(__float_as_uint(b0)), "r"(__float_as_uint(b1)));
}

__device__ __forceinline__ void cpa16(uint32_t saddr, const void* g) {
    asm volatile("cp.async.cg.shared.global [%0], [%1], 16;" :: "r"(saddr), "l"(g));
}
__device__ __forceinline__ void cpa_commit() {
    asm volatile("cp.async.commit_group;");
}
template <int N>
__device__ __forceinline__ void cpa_wait() {
    asm volatile("cp.async.wait_group %0;" :: "n"(N));
}

#define SA_STRIDE 36    // fragment bank = (4g+t+kb)%32: conflict-free
#define SB_STRIDE 36
#define EB_STRIDE 260   // persistent B rows: 260%32=4 -> same permutation

// ---------------------------------------------------------------------------
// Kernel 0: init — tf32-round weights AND reset work-steal counters.
// ---------------------------------------------------------------------------
__global__ void init_kernel(
    const float* __restrict__ Wu, const float* __restrict__ Wv,
    const float* __restrict__ Wa, const float* __restrict__ Wb,
    const float* __restrict__ Wc)
{
    int i = blockIdx.x * blockDim.x + threadIdx.x;
    if (i < 2) g_tile_ctr[i] = 0;
    int m = i >> 14;
    int r = i & 16383;
    const float* src = (m == 0) ? Wu : (m == 1) ? Wv : (m == 2) ? Wa : (m == 3) ? Wb : Wc;
    float4 v = __ldg(reinterpret_cast<const float4*>(src) + r);
    reinterpret_cast<float4*>(g_wtf)[i] = tf32_4(v);
}

// ---------------------------------------------------------------------------
// Kernel 1: node GEMM (2 CTAs/SM). by==0 (Uh) writes into g_agg directly —
// this replaces zero_agg; edge_epilogue's atomics land on top (stream order).
// ---------------------------------------------------------------------------
#define NG_SA0 0
#define NG_SA1 2304
#define NG_SB0 4608
#define NG_SB1 13824
#define NG_SMEM_BYTES 92160

__global__ __launch_bounds__(256, 2) void node_gemm_tc_kernel(
    const float* __restrict__ h,
    const float* __restrict__ bu, const float* __restrict__ bv,
    const float* __restrict__ ba, const float* __restrict__ bb,
    int V)
{
    extern __shared__ float smem[];
    const uint32_t smem_u32 = (uint32_t)__cvta_generic_to_shared(smem);

    const int by = blockIdx.y;
    const float* W = g_wtf + (size_t)by * 65536;
    const float* bias = (by == 0) ? bu : (by == 1) ? bv : (by == 2) ? ba : bb;

    const int tid  = threadIdx.x;
    const int w    = tid >> 5;
    const int lane = tid & 31;
    const int g    = lane >> 2;
    const int t    = lane & 3;
    const int row0 = blockIdx.x * 64;

    const int lr  = tid >> 2;
    const int lk8 = (tid & 3) * 8;

    int gr = row0 + lr; if (gr >= V) gr = V - 1;
    const float* arow = h + (size_t)gr * H_DIM + lk8;
    const float* brow = W + (size_t)tid * H_DIM;

    const uint32_t sa_a[2] = { smem_u32 + (NG_SA0 + lr * SA_STRIDE + lk8) * 4,
                               smem_u32 + (NG_SA1 + lr * SA_STRIDE + lk8) * 4 };
    const uint32_t sb_a[2] = { smem_u32 + (NG_SB0 + tid * SB_STRIDE) * 4,
                               smem_u32 + (NG_SB1 + tid * SB_STRIDE) * 4 };

    float acc[4][4][4];
    #pragma unroll
    for (int mt = 0; mt < 4; mt++)
        #pragma unroll
        for (int nt = 0; nt < 4; nt++)
            #pragma unroll
            for (int q = 0; q < 4; q++) acc[mt][nt][q] = 0.f;

    cpa16(sa_a[0],      arow);
    cpa16(sa_a[0] + 16, arow + 4);
    #pragma unroll
    for (int q = 0; q < 8; q++) cpa16(sb_a[0] + q * 16, brow + q * 4);
    cpa_commit();

    #pragma unroll
    for (int c = 0; c < 8; c++) {
        const int buf = c & 1;
        if (c < 7) {
            const int nbuf = buf ^ 1;
            const int kk = (c + 1) * 32;
            cpa16(sa_a[nbuf],      arow + kk);
            cpa16(sa_a[nbuf] + 16, arow + kk + 4);
            #pragma unroll
            for (int q = 0; q < 8; q++) cpa16(sb_a[nbuf] + q * 16, brow + kk + q * 4);
            cpa_commit();
            cpa_wait<1>();
        } else {
            cpa_wait<0>();
        }
        __syncthreads();

        const float* sA = smem + (buf ? NG_SA1 : NG_SA0);
        const float* sB = smem + (buf ? NG_SB1 : NG_SB0);
        #pragma unroll
        for (int ks = 0; ks < 4; ks++) {
            const int kb = ks * 8;
            float bf[4][2];
            #pragma unroll
            for (int nt = 0; nt < 4; nt++) {
                int n = w * 32 + nt * 8 + g;
                bf[nt][0] = sB[n * SB_STRIDE + kb + t];
                bf[nt][1] = sB[n * SB_STRIDE + kb + t + 4];
            }
            #pragma unroll
            for (int mt = 0; mt < 4; mt++) {
                int m = mt * 16;
                float a0 = sA[(m + g) * SA_STRIDE + kb + t];
                float a1 = sA[(m + g + 8) * SA_STRIDE + kb + t];
                float a2 = sA[(m + g) * SA_STRIDE + kb + t + 4];
                float a3 = sA[(m + g + 8) * SA_STRIDE + kb + t + 4];
                #pragma unroll
                for (int nt = 0; nt < 4; nt++)
                    mma_tf32(acc[mt][nt][0], acc[mt][nt][1], acc[mt][nt][2], acc[mt][nt][3],
                             a0, a1, a2, a3, bf[nt][0], bf[nt][1]);
            }
        }
        __syncthreads();
    }

    #pragma unroll
    for (int mt = 0; mt < 4; mt++) {
        #pragma unroll
        for (int nt = 0; nt < 4; nt++) {
            int cc = w * 32 + nt * 8 + 2 * t;
            int r0 = row0 + mt * 16 + g;
            int r1 = r0 + 8;
            if (r0 < V) {
                float* o = (by == 0) ? (g_agg + (size_t)r0 * H_DIM + cc)
                                     : (g_nodebuf + (size_t)r0 * 1024 + by * 256 + cc);
                o[0] = acc[mt][nt][0] + bias[cc];
                o[1] = acc[mt][nt][1] + bias[cc + 1];
            }
            if (r1 < V) {
                float* o = (by == 0) ? (g_agg + (size_t)r1 * H_DIM + cc)
                                     : (g_nodebuf + (size_t)r1 * 1024 + by * 256 + cc);
                o[0] = acc[mt][nt][2] + bias[cc];
                o[1] = acc[mt][nt][3] + bias[cc + 1];
            }
        }
    }
}

// ---------------------------------------------------------------------------
// Kernel 2a: persistent-B edge GEMM, 512 threads, 256x128 tile, work-stealing.
// ---------------------------------------------------------------------------
#define EG_B_OFF 0
#define EG_A_OFF 33280
#define EG_A_BUF 9216
#define EG_SMEM_BYTES 206848

__global__ __launch_bounds__(512, 1) void edge_gemm_kernel(
    const float* __restrict__ e, int E)
{
    extern __shared__ float smem[];
    const uint32_t smem_u32 = (uint32_t)__cvta_generic_to_shared(smem);
    __shared__ int s_tile;

    const int nb = blockIdx.x;                 // 128-col half of Wc
    const int tid  = threadIdx.x;
    const int w    = tid >> 5;
    const int lane = tid & 31;
    const int g    = lane >> 2;
    const int t    = lane & 3;
    const int wm   = w >> 1;
    const int wn   = w & 1;

    const int ar0 = tid >> 3;
    const int aq  = (tid & 7) * 4;

    const int nTiles = E / 256;

    // persistent B half
    {
        const float* Wcv = g_wtf + 4 * 65536 + (size_t)(nb * 128) * H_DIM;
        #pragma unroll
        for (int i = 0; i < 16; i++) {
            int fi = tid + i * 512;
            int n  = fi >> 6;
            int q  = fi & 63;
            cpa16(smem_u32 + (EG_B_OFF + n * EB_STRIDE + q * 4) * 4,
                  Wcv + (size_t)n * H_DIM + q * 4);
        }
        cpa_commit();
    }

    const uint32_t sa_base[2] = {
        smem_u32 + (EG_A_OFF + 0 * EG_A_BUF + ar0 * SA_STRIDE + aq) * 4,
        smem_u32 + (EG_A_OFF + 1 * EG_A_BUF + ar0 * SA_STRIDE + aq) * 4 };
    const float* sB = smem + EG_B_OFF;

    while (true) {
        if (tid == 0) s_tile = atomicAdd(&g_tile_ctr[nb], 1);
        __syncthreads();
        const int ti = s_tile;
        if (ti >= nTiles) break;

        const int e0 = ti * 256;
        const float* abase = e + (size_t)(e0 + ar0) * H_DIM + aq;

        float acc[2][8][4];
        #pragma unroll
        for (int mt = 0; mt < 2; mt++)
            #pragma unroll
            for (int nt = 0; nt < 8; nt++)
                #pragma unroll
                for (int q = 0; q < 4; q++) acc[mt][nt][q] = 0.f;

        #pragma unroll
        for (int i = 0; i < 4; i++)
            cpa16(sa_base[0] + i * 64 * SA_STRIDE * 4, abase + (size_t)i * 64 * H_DIM);
        cpa_commit();

        #pragma unroll
        for (int c = 0; c < 8; c++) {
            if (c < 7) {
                const int nbuf = (c + 1) & 1;
                const int kk = (c + 1) * 32;
                #pragma unroll
                for (int i = 0; i < 4; i++)
                    cpa16(sa_base[nbuf] + i * 64 * SA_STRIDE * 4,
                          abase + (size_t)i * 64 * H_DIM + kk);
                cpa_commit();
                cpa_wait<1>();
            } else {
                cpa_wait<0>();
            }
            __syncthreads();

            const float* sA = smem + EG_A_OFF + (c & 1) * EG_A_BUF;
            const int kg = c * 32;
            #pragma unroll
            for (int ks = 0; ks < 4; ks++) {
                const int kb = ks * 8;
                float bf[8][2];
                #pragma unroll
                for (int nt = 0; nt < 8; nt++) {
                    int n = wn * 64 + nt * 8 + g;
                    bf[nt][0] = sB[n * EB_STRIDE + kg + kb + t];
                    bf[nt][1] = sB[n * EB_STRIDE + kg + kb + t + 4];
                }
                #pragma unroll
                for (int mt = 0; mt < 2; mt++) {
                    int m = wm * 32 + mt * 16;
                    float a0 = sA[(m + g) * SA_STRIDE + kb + t];
                    float a1 = sA[(m + g + 8) * SA_STRIDE + kb + t];
                    float a2 = sA[(m + g) * SA_STRIDE + kb + t + 4];
                    float a3 = sA[(m + g + 8) * SA_STRIDE + kb + t + 4];
                    #pragma unroll
                    for (int nt = 0; nt < 8; nt++)
                        mma_tf32(acc[mt][nt][0], acc[mt][nt][1], acc[mt][nt][2], acc[mt][nt][3],
                                 a0, a1, a2, a3, bf[nt][0], bf[nt][1]);
                }
            }
            __syncthreads();
        }

        #pragma unroll
        for (int mt = 0; mt < 2; mt++) {
            #pragma unroll
            for (int nt = 0; nt < 8; nt++) {
                int col = nb * 128 + wn * 64 + nt * 8 + 2 * t;
                int r0 = wm * 32 + mt * 16 + g;
                float* o0 = g_ce + (size_t)(e0 + r0) * H_DIM + col;
                float* o1 = g_ce + (size_t)(e0 + r0 + 8) * H_DIM + col;
                __stcs(reinterpret_cast<float2*>(o0), make_float2(acc[mt][nt][0], acc[mt][nt][1]));
                __stcs(reinterpret_cast<float2*>(o1), make_float2(acc[mt][nt][2], acc[mt][nt][3]));
            }
        }
    }
}

// ---------------------------------------------------------------------------
// Kernel 2b: edge epilogue (one warp per edge; high occupancy)
// ---------------------------------------------------------------------------
__global__ __launch_bounds__(256) void edge_epilogue_kernel(
    const float* __restrict__ e,
    const int*   __restrict__ ei,
    const float* __restrict__ bc,
    const float* __restrict__ ge, const float* __restrict__ be,
    float* __restrict__ e_out,
    int E)
{
    __shared__ float sBc[256], sGe[256], sBe[256];
    const int tid = threadIdx.x;
    sBc[tid] = bc[tid]; sGe[tid] = ge[tid]; sBe[tid] = be[tid];
    __syncthreads();

    const int warp = tid >> 5;
    const int lane = tid & 31;
    const int col0 = lane * 8;
    const int er = blockIdx.x * 8 + warp;

    const int s = __ldg(ei + er);
    const int d = __ldg(ei + E + er);

    const float4* cep = reinterpret_cast<const float4*>(g_ce + (size_t)er * H_DIM + col0);
    const float4* ah = reinterpret_cast<const float4*>(g_nodebuf + (size_t)d * 1024 + 512 + col0);
    const float4* bh = reinterpret_cast<const float4*>(g_nodebuf + (size_t)s * 1024 + 768 + col0);
    const float4* vh = reinterpret_cast<const float4*>(g_nodebuf + (size_t)d * 1024 + 256 + col0);
    const float4* erp = reinterpret_cast<const float4*>(e + (size_t)er * H_DIM + col0);

    float4 c0 = __ldcs(cep), c1 = __ldcs(cep + 1);
    float4 a0 = __ldg(ah),   a1 = __ldg(ah + 1);
    float4 b0 = __ldg(bh),   b1 = __ldg(bh + 1);
    float4 v0 = __ldg(vh),   v1 = __ldg(vh + 1);
    float4 r0 = __ldcs(erp), r1 = __ldcs(erp + 1);

    float x[8], vhv[8], erv[8];
    x[0] = c0.x + a0.x + b0.x; x[1] = c0.y + a0.y + b0.y;
    x[2] = c0.z + a0.z + b0.z; x[3] = c0.w + a0.w + b0.w;
    x[4] = c1.x + a1.x + b1.x; x[5] = c1.y + a1.y + b1.y;
    x[6] = c1.z + a1.z + b1.z; x[7] = c1.w + a1.w + b1.w;
    vhv[0] = v0.x; vhv[1] = v0.y; vhv[2] = v0.z; vhv[3] = v0.w;
    vhv[4] = v1.x; vhv[5] = v1.y; vhv[6] = v1.z; vhv[7] = v1.w;
    erv[0] = r0.x; erv[1] = r0.y; erv[2] = r0.z; erv[3] = r0.w;
    erv[4] = r1.x; erv[5] = r1.y; erv[6] = r1.z; erv[7] = r1.w;

    float sum = 0.f, sq = 0.f;
    #pragma unroll
    for (int c = 0; c < 8; c++) {
        float xv = x[c] + sBc[col0 + c];
        x[c] = xv;
        sum += xv;
        sq  += xv * xv;
    }

    float gv[8];
    #pragma unroll
    for (int c = 0; c < 8; c++) {
        float gt = 1.f / (1.f + __expf(-x[c]));
        gv[c] = gt * vhv[c];
    }
    float* ag = g_agg + (size_t)s * H_DIM + col0;
    red_add_v4(ag,     gv[0], gv[1], gv[2], gv[3]);
    red_add_v4(ag + 4, gv[4], gv[5], gv[6], gv[7]);

    #pragma unroll
    for (int off = 16; off > 0; off >>= 1) {
        sum += __shfl_xor_sync(0xFFFFFFFFu, sum, off);
        sq  += __shfl_xor_sync(0xFFFFFFFFu, sq,  off);
    }
    const float mu  = sum * (1.f / 256.f);
    const float var = sq * (1.f / 256.f) - mu * mu;
    const float rs  = rsqrtf(var + LN_EPS);

    float4 o0, o1;
    float* ov0 = &o0.x; float* ov1 = &o1.x;
    #pragma unroll
    for (int c = 0; c < 4; c++) {
        float y = (x[c] - mu) * rs * sGe[col0 + c] + sBe[col0 + c];
        y = y > 0.f ? y : 0.f;
        ov0[c] = erv[c] + y;
    }
    #pragma unroll
    for (int c = 0; c < 4; c++) {
        float y = (x[c + 4] - mu) * rs * sGe[col0 + c + 4] + sBe[col0 + c + 4];
        y = y > 0.f ? y : 0.f;
        ov1[c] = erv[c + 4] + y;
    }
    float4* orow = reinterpret_cast<float4*>(e_out + (size_t)er * H_DIM + col0);
    __stcs(orow, o0);
    __stcs(orow + 1, o1);
}

// ---------------------------------------------------------------------------
// Kernel 3: node epilogue — g_agg already holds Uh + bias + agg.
// ---------------------------------------------------------------------------
__global__ __launch_bounds__(256) void node_epilogue_kernel(
    const float* __restrict__ h,
    const float* __restrict__ gh, const float* __restrict__ bhv,
    float* __restrict__ h_out, int V)
{
    const int warp = threadIdx.x >> 5;
    const int lane = threadIdx.x & 31;
    const int n = blockIdx.x * 8 + warp;
    if (n >= V) return;
    const int col0 = lane * 8;

    const float4* ag = reinterpret_cast<const float4*>(g_agg + (size_t)n * H_DIM + col0);
    const float4* hr = reinterpret_cast<const float4*>(h     + (size_t)n * H_DIM + col0);

    float4 g0 = __ldcs(ag), g1 = __ldcs(ag + 1);
    float4 h0 = __ldcs(hr), h1 = __ldcs(hr + 1);

    float x[8], hv[8];
    x[0] = g0.x; x[1] = g0.y; x[2] = g0.z; x[3] = g0.w;
    x[4] = g1.x; x[5] = g1.y; x[6] = g1.z; x[7] = g1.w;
    hv[0] = h0.x; hv[1] = h0.y; hv[2] = h0.z; hv[3] = h0.w;
    hv[4] = h1.x; hv[5] = h1.y; hv[6] = h1.z; hv[7] = h1.w;

    float sum = 0.f, sq = 0.f;
    #pragma unroll
    for (int c = 0; c < 8; c++) { sum += x[c]; sq += x[c] * x[c]; }
    #pragma unroll
    for (int off = 16; off > 0; off >>= 1) {
        sum += __shfl_xor_sync(0xFFFFFFFFu, sum, off);
        sq  += __shfl_xor_sync(0xFFFFFFFFu, sq,  off);
    }
    const float mu  = sum * (1.f / 256.f);
    const float var = sq * (1.f / 256.f) - mu * mu;
    const float rs  = rsqrtf(var + LN_EPS);

    float4 o0, o1;
    float* ov0 = &o0.x; float* ov1 = &o1.x;
    #pragma unroll
    for (int c = 0; c < 4; c++) {
        float y = (x[c] - mu) * rs * gh[col0 + c] + bhv[col0 + c];
        y = y > 0.f ? y : 0.f;
        ov0[c] = hv[c] + y;
    }
    #pragma unroll
    for (int c = 0; c < 4; c++) {
        float y = (x[c + 4] - mu) * rs * gh[col0 + c + 4] + bhv[col0 + c + 4];
        y = y > 0.f ? y : 0.f;
        ov1[c] = hv[c + 4] + y;
    }
    float4* o = reinterpret_cast<float4*>(h_out + (size_t)n * H_DIM + col0);
    __stcs(o, o0);
    __stcs(o + 1, o1);
}

// ---------------------------------------------------------------------------
extern "C" void kernel_launch(void* const* d_in, const int* in_sizes, int n_in,
                              void* d_out, int out_size)
{
    const float* h  = (const float*)d_in[0];
    const float* e  = (const float*)d_in[1];
    const int*   ei = (const int*)  d_in[2];
    const float* Wu = (const float*)d_in[3];
    const float* bu = (const float*)d_in[4];
    const float* Wv = (const float*)d_in[5];
    const float* bv = (const float*)d_in[6];
    const float* Wa = (const float*)d_in[7];
    const float* ba = (const float*)d_in[8];
    const float* Wb = (const float*)d_in[9];
    const float* bb = (const float*)d_in[10];
    const float* Wc = (const float*)d_in[11];
    const float* bc = (const float*)d_in[12];
    const float* gh = (const float*)d_in[13];
    const float* bh = (const float*)d_in[14];
    const float* ge = (const float*)d_in[15];
    const float* be = (const float*)d_in[16];

    const int V = in_sizes[0] / H_DIM;
    const int E = in_sizes[1] / H_DIM;

    float* h_out = (float*)d_out;
    float* e_out = (float*)d_out + (size_t)V * H_DIM;

    static int attr_set = 0;
    if (!attr_set) {
        cudaFuncSetAttribute(node_gemm_tc_kernel,
                             cudaFuncAttributeMaxDynamicSharedMemorySize, NG_SMEM_BYTES);
        cudaFuncSetAttribute(edge_gemm_kernel,
                             cudaFuncAttributeMaxDynamicSharedMemorySize, EG_SMEM_BYTES);
        attr_set = 1;
    }

    init_kernel<<<320, 256>>>(Wu, Wv, Wa, Wb, Wc);

    dim3 g1((V + 63) / 64, 4);
    node_gemm_tc_kernel<<<g1, 256, NG_SMEM_BYTES>>>(h, bu, bv, ba, bb, V);

    dim3 g2(2, 74);   // persistent; work-steal over 625 tiles per half
    edge_gemm_kernel<<<g2, 512, EG_SMEM_BYTES>>>(e, E);

    edge_epilogue_kernel<<<E / 8, 256>>>(e, ei, bc, ge, be, e_out, E);

    node_epilogue_kernel<<<(V + 7) / 8, 256>>>(h, gh, bh, h_out, V);
}